// round 13
// baseline (speedup 1.0000x reference)
#include <cuda_runtime.h>
#include <cuda_bf16.h>
#include <cstdint>

// ---------------- Problem constants ----------------
#define NB   8
#define LQ   1000
#define NQ   (NB*LQ)
#define DIM  256
#define HEADS 8
#define HD   32
#define LIN  21760
#define DFF  512
#define NOA  384

__device__ __constant__ int c_H[4]  = {128, 64, 32, 16};
__device__ __constant__ int c_W[4]  = {128, 64, 32, 16};
__device__ __constant__ int c_S[4]  = {0, 16384, 20480, 21504};

// ---------------- Scratch ----------------
__device__ __nv_bfloat16 g_value[(size_t)LIN * NB * DIM];
__device__ float g_oa   [(size_t)NQ * NOA];
__device__ float g_samp [(size_t)NQ * DIM];
__device__ float g_ms   [(size_t)NQ * DIM];
__device__ float g_tgt  [(size_t)NQ * DIM];
__device__ float g_ffh  [(size_t)NQ * DFF];
__device__ float g_ff   [(size_t)NQ * DIM];
__device__ __nv_bfloat16 g_WvTb [DIM * DIM];
__device__ __nv_bfloat16 g_WoutTb[DIM * DIM];
__device__ __nv_bfloat16 g_W1Tb [DFF * DIM];
__device__ __nv_bfloat16 g_W2Tb [DIM * DFF];
__device__ __nv_bfloat16 g_WoaTh[NOA * DIM];
__device__ __nv_bfloat16 g_WoaTl[NOA * DIM];
__device__ float g_boa  [NOA];

// ---------------- helpers ----------------
__device__ __forceinline__ void mma_bf16(float* d, const uint32_t* a, const uint32_t* b) {
    asm volatile(
        "mma.sync.aligned.m16n8k16.row.col.f32.bf16.bf16.f32 "
        "{%0,%1,%2,%3}, {%4,%5,%6,%7}, {%8,%9}, {%0,%1,%2,%3};"
        : "+f"(d[0]), "+f"(d[1]), "+f"(d[2]), "+f"(d[3])
        : "r"(a[0]), "r"(a[1]), "r"(a[2]), "r"(a[3]), "r"(b[0]), "r"(b[1]));
}
__device__ __forceinline__ void ldmx4(uint32_t* r, uint32_t addr) {
    asm volatile("ldmatrix.sync.aligned.m8n8.x4.shared.b16 {%0,%1,%2,%3}, [%4];"
        : "=r"(r[0]), "=r"(r[1]), "=r"(r[2]), "=r"(r[3]) : "r"(addr));
}
__device__ __forceinline__ uint32_t packbf(float lo, float hi) {
    __nv_bfloat162 h = __floats2bfloat162_rn(lo, hi);
    return *reinterpret_cast<uint32_t*>(&h);
}
__device__ __forceinline__ void cpa16(uint32_t dst, const void* src) {
    asm volatile("cp.async.cg.shared.global [%0], [%1], 16;" :: "r"(dst), "l"(src) : "memory");
}
#define CPA_COMMIT() asm volatile("cp.async.commit_group;" ::: "memory")
#define CPA_WAIT0()  asm volatile("cp.async.wait_group 0;"  ::: "memory")
#define SW64(o) ((uint32_t)(o) ^ (((uint32_t)(o) >> 3) & 0x30u))

// ================= bf16 mma GEMM v7: C = A(fp32) @ Bb(bf16,[N,K])^T + bias =========
// BM=64, BN=128, BK=32. 256 threads (8 warps 2x4, warp tile 32x32).
// smem 24KB, 3 CTAs/SM forced. K mult of 32, N mult of 128, M mult of 64.
template<int ACT, bool MASK, int OUT>
__global__ void __launch_bounds__(256, 3) mma_gemm_v7(
    const float* __restrict__ A, const __nv_bfloat16* __restrict__ Bb,
    const float* __restrict__ bias, void* __restrict__ Cv,
    int M, int N, int K, const unsigned char* __restrict__ rowmask)
{
    __shared__ __align__(128) __nv_bfloat16 As[2][64 * 32];    // 2 x 4 KB
    __shared__ __align__(128) __nv_bfloat16 Bs[2][128 * 32];   // 2 x 8 KB

    const int tid  = threadIdx.x;
    const int lane = tid & 31;
    const int wid  = tid >> 5;
    const int wr   = wid & 1;       // 2 warp rows of 32
    const int wc   = wid >> 1;      // 4 warp cols of 32
    const int gid  = lane >> 2;
    const int tig  = lane & 3;
    const int brow = blockIdx.y * 64;
    const int bcol = blockIdx.x * 128;

    const int r_st = tid >> 3;          // 0..31
    const int kq   = (tid & 7) * 4;
    const int sts_col = (tid & 7) * 8;
    const int b_row_cp = tid >> 2;
    const int b_cg     = (tid & 3);

    float acc[2][4][4];
    #pragma unroll
    for (int i = 0; i < 2; i++)
        #pragma unroll
        for (int j = 0; j < 4; j++)
            #pragma unroll
            for (int l = 0; l < 4; l++) acc[i][j][l] = 0.f;

    const uint32_t asb = (uint32_t)__cvta_generic_to_shared(&As[0][0]);
    const uint32_t bsb = (uint32_t)__cvta_generic_to_shared(&Bs[0][0]);
    const uint32_t abufoff = 64 * 32 * 2;
    const uint32_t bbufoff = 128 * 32 * 2;

    const int a_row = (lane & 7) + ((lane >> 3) & 1) * 8;
    const int a_col = (lane >> 4) * 16;
    const int b_row = (lane & 7) + ((lane >> 4) & 1) * 8;
    const int b_col = ((lane >> 3) & 1) * 16;

    uint2 pa[2];

    #define LD_A(kc) do {                                                               \
        _Pragma("unroll")                                                               \
        for (int i = 0; i < 2; i++) {                                                   \
            int gr = brow + r_st + 32 * i; if (gr >= M) gr = M - 1;                     \
            float4 v = *reinterpret_cast<const float4*>(A + (size_t)gr * K + (kc) + kq);\
            pa[i].x = packbf(v.x, v.y); pa[i].y = packbf(v.z, v.w);                     \
        }                                                                               \
    } while (0)

    #define ST_A(buf) do {                                                              \
        char* sa = reinterpret_cast<char*>(&As[buf][0]);                                \
        _Pragma("unroll")                                                               \
        for (int i = 0; i < 2; i++)                                                     \
            *reinterpret_cast<uint2*>(sa + SW64((r_st + 32 * i) * 64 + sts_col)) = pa[i];\
    } while (0)

    #define CPA_B(kc, buf) do {                                                         \
        _Pragma("unroll")                                                               \
        for (int j = 0; j < 2; j++) {                                                   \
            int row = b_row_cp + 64 * j;                                                \
            cpa16(bsb + (buf) * bbufoff + SW64(row * 64 + b_cg * 16),                   \
                  Bb + (size_t)(bcol + row) * K + (kc) + b_cg * 8);                     \
        }                                                                               \
    } while (0)

    const int KT = K >> 5;
    CPA_B(0, 0);
    CPA_COMMIT();
    LD_A(0);
    ST_A(0);
    CPA_WAIT0();
    __syncthreads();

    for (int kt = 0; kt < KT; kt++) {
        const int buf = kt & 1;
        if (kt + 1 < KT) {
            CPA_B((kt + 1) * 32, buf ^ 1);
            CPA_COMMIT();
            LD_A((kt + 1) * 32);
        }

        const uint32_t ab = asb + buf * abufoff;
        const uint32_t bb = bsb + buf * bbufoff;
        #pragma unroll
        for (int ks = 0; ks < 2; ks++) {
            uint32_t af[2][4], bfq[2][4];
            #pragma unroll
            for (int mt = 0; mt < 2; mt++)
                ldmx4(af[mt], ab + SW64((wr * 32 + mt * 16 + a_row) * 64 + a_col + ks * 32));
            #pragma unroll
            for (int p = 0; p < 2; p++)
                ldmx4(bfq[p], bb + SW64((wc * 32 + p * 16 + b_row) * 64 + b_col + ks * 32));
            #pragma unroll
            for (int mt = 0; mt < 2; mt++)
                #pragma unroll
                for (int nt = 0; nt < 4; nt++)
                    mma_bf16(acc[mt][nt], af[mt], &bfq[nt >> 1][(nt & 1) * 2]);
        }

        if (kt + 1 < KT) {
            ST_A(buf ^ 1);
            CPA_WAIT0();
            __syncthreads();
        }
    }
    #undef LD_A
    #undef ST_A
    #undef CPA_B

    float* Cf = (float*)Cv;
    __nv_bfloat16* Cb = (__nv_bfloat16*)Cv;

    #pragma unroll
    for (int mt = 0; mt < 2; mt++) {
        const int r0 = brow + wr * 32 + mt * 16 + gid;
        const int r1 = r0 + 8;
        const bool v0 = r0 < M, v1 = r1 < M;
        bool z0 = false, z1 = false;
        if (MASK) {
            if (v0) z0 = (rowmask[r0] != 0);
            if (v1) z1 = (rowmask[r1] != 0);
        }
        #pragma unroll
        for (int nt = 0; nt < 4; nt++) {
            const int col = bcol + wc * 32 + nt * 8 + 2 * tig;
            const float b0 = bias[col], b1 = bias[col + 1];
            float2 u, v;
            u.x = acc[mt][nt][0] + b0; u.y = acc[mt][nt][1] + b1;
            v.x = acc[mt][nt][2] + b0; v.y = acc[mt][nt][3] + b1;
            if (ACT == 1) {
                u.x = fmaxf(u.x, 0.f); u.y = fmaxf(u.y, 0.f);
                v.x = fmaxf(v.x, 0.f); v.y = fmaxf(v.y, 0.f);
            }
            if (MASK) {
                if (z0) { u.x = 0.f; u.y = 0.f; }
                if (z1) { v.x = 0.f; v.y = 0.f; }
            }
            if (OUT == 0) {
                if (v0) *reinterpret_cast<float2*>(Cf + (size_t)r0 * N + col) = u;
                if (v1) *reinterpret_cast<float2*>(Cf + (size_t)r1 * N + col) = v;
            } else {
                __nv_bfloat162 hu = __floats2bfloat162_rn(u.x, u.y);
                __nv_bfloat162 hv = __floats2bfloat162_rn(v.x, v.y);
                if (v0) *reinterpret_cast<__nv_bfloat162*>(Cb + (size_t)r0 * N + col) = hu;
                if (v1) *reinterpret_cast<__nv_bfloat162*>(Cb + (size_t)r1 * N + col) = hv;
            }
        }
    }
}

// ================= bf16x3 GEMM (oa): ~fp32 precision =================
__global__ void __launch_bounds__(256, 2) mma_gemm_x3(
    const float* __restrict__ A, const float* __restrict__ A2,
    const __nv_bfloat16* __restrict__ Bh, const __nv_bfloat16* __restrict__ Bl,
    const float* __restrict__ bias, float* __restrict__ C,
    int M, int N, int K)
{
    __shared__ __align__(128) __nv_bfloat16 Ahs[128 * 32];
    __shared__ __align__(128) __nv_bfloat16 Als[128 * 32];
    __shared__ __align__(128) __nv_bfloat16 Bhs[128 * 32];
    __shared__ __align__(128) __nv_bfloat16 Bls[128 * 32];

    const int tid  = threadIdx.x;
    const int lane = tid & 31;
    const int wid  = tid >> 5;
    const int wr   = wid & 1;
    const int wc   = wid >> 1;
    const int gid  = lane >> 2;
    const int tig  = lane & 3;
    const int brow = blockIdx.y * 128;
    const int bcol = blockIdx.x * 128;

    const int r_st = tid >> 3;
    const int kq   = (tid & 7) * 4;
    const int sts_col = (tid & 7) * 8;
    const int b_row_cp = tid >> 2;
    const int b_cg     = (tid & 3);

    float acc[4][4][4];
    #pragma unroll
    for (int i = 0; i < 4; i++)
        #pragma unroll
        for (int j = 0; j < 4; j++)
            #pragma unroll
            for (int l = 0; l < 4; l++) acc[i][j][l] = 0.f;

    const uint32_t ahb = (uint32_t)__cvta_generic_to_shared(&Ahs[0]);
    const uint32_t alb = (uint32_t)__cvta_generic_to_shared(&Als[0]);
    const uint32_t bhb = (uint32_t)__cvta_generic_to_shared(&Bhs[0]);
    const uint32_t blb = (uint32_t)__cvta_generic_to_shared(&Bls[0]);

    const int a_row = (lane & 7) + ((lane >> 3) & 1) * 8;
    const int a_col = (lane >> 4) * 16;
    const int b_row = (lane & 7) + ((lane >> 4) & 1) * 8;
    const int b_col = ((lane >> 3) & 1) * 16;

    uint2 pah[4], pal[4];

    #define LD_AX(kc) do {                                                              \
        _Pragma("unroll")                                                               \
        for (int i = 0; i < 4; i++) {                                                   \
            int gr = brow + r_st + 32 * i; if (gr >= M) gr = M - 1;                     \
            float4 v  = *reinterpret_cast<const float4*>(A  + (size_t)gr * K + (kc) + kq);\
            float4 v2 = *reinterpret_cast<const float4*>(A2 + (size_t)gr * K + (kc) + kq);\
            v.x += v2.x; v.y += v2.y; v.z += v2.z; v.w += v2.w;                         \
            __nv_bfloat162 h0 = __floats2bfloat162_rn(v.x, v.y);                        \
            __nv_bfloat162 h1 = __floats2bfloat162_rn(v.z, v.w);                        \
            float2 f0 = __bfloat1622float2(h0);                                         \
            float2 f1 = __bfloat1622float2(h1);                                         \
            pah[i].x = *reinterpret_cast<uint32_t*>(&h0);                               \
            pah[i].y = *reinterpret_cast<uint32_t*>(&h1);                               \
            pal[i].x = packbf(v.x - f0.x, v.y - f0.y);                                  \
            pal[i].y = packbf(v.z - f1.x, v.w - f1.y);                                  \
        }                                                                               \
    } while (0)

    #define ST_AX() do {                                                                \
        char* sh = reinterpret_cast<char*>(&Ahs[0]);                                    \
        char* sl = reinterpret_cast<char*>(&Als[0]);                                    \
        _Pragma("unroll")                                                               \
        for (int i = 0; i < 4; i++) {                                                   \
            uint32_t o = SW64((r_st + 32 * i) * 64 + sts_col);                          \
            *reinterpret_cast<uint2*>(sh + o) = pah[i];                                 \
            *reinterpret_cast<uint2*>(sl + o) = pal[i];                                 \
        }                                                                               \
    } while (0)

    #define CPA_BX(kc) do {                                                             \
        _Pragma("unroll")                                                               \
        for (int j = 0; j < 2; j++) {                                                   \
            int row = b_row_cp + 64 * j;                                                \
            uint32_t o = SW64(row * 64 + b_cg * 16);                                    \
            size_t gsrc = (size_t)(bcol + row) * K + (kc) + b_cg * 8;                   \
            cpa16(bhb + o, Bh + gsrc);                                                  \
            cpa16(blb + o, Bl + gsrc);                                                  \
        }                                                                               \
    } while (0)

    const int KT = K >> 5;
    LD_AX(0);
    for (int kt = 0; kt < KT; kt++) {
        if (kt) __syncthreads();
        ST_AX();
        CPA_BX(kt * 32);
        CPA_COMMIT();
        if (kt + 1 < KT) LD_AX((kt + 1) * 32);
        CPA_WAIT0();
        __syncthreads();

        #pragma unroll
        for (int ks = 0; ks < 2; ks++) {
            uint32_t afh[4][4], bfh[2][4];
            #pragma unroll
            for (int mt = 0; mt < 4; mt++)
                ldmx4(afh[mt], ahb + SW64((wr * 64 + mt * 16 + a_row) * 64 + a_col + ks * 32));
            #pragma unroll
            for (int p = 0; p < 2; p++)
                ldmx4(bfh[p], bhb + SW64((wc * 32 + p * 16 + b_row) * 64 + b_col + ks * 32));
            #pragma unroll
            for (int mt = 0; mt < 4; mt++)
                #pragma unroll
                for (int nt = 0; nt < 4; nt++)
                    mma_bf16(acc[mt][nt], afh[mt], &bfh[nt >> 1][(nt & 1) * 2]);

            {
                uint32_t bfl[2][4];
                #pragma unroll
                for (int p = 0; p < 2; p++)
                    ldmx4(bfl[p], blb + SW64((wc * 32 + p * 16 + b_row) * 64 + b_col + ks * 32));
                #pragma unroll
                for (int mt = 0; mt < 4; mt++)
                    #pragma unroll
                    for (int nt = 0; nt < 4; nt++)
                        mma_bf16(acc[mt][nt], afh[mt], &bfl[nt >> 1][(nt & 1) * 2]);
            }
            {
                uint32_t afl[4][4];
                #pragma unroll
                for (int mt = 0; mt < 4; mt++)
                    ldmx4(afl[mt], alb + SW64((wr * 64 + mt * 16 + a_row) * 64 + a_col + ks * 32));
                #pragma unroll
                for (int mt = 0; mt < 4; mt++)
                    #pragma unroll
                    for (int nt = 0; nt < 4; nt++)
                        mma_bf16(acc[mt][nt], afl[mt], &bfh[nt >> 1][(nt & 1) * 2]);
            }
        }
    }
    #undef LD_AX
    #undef ST_AX
    #undef CPA_BX

    #pragma unroll
    for (int mt = 0; mt < 4; mt++) {
        const int r0 = brow + wr * 64 + mt * 16 + gid;
        const int r1 = r0 + 8;
        const bool v0 = r0 < M, v1 = r1 < M;
        #pragma unroll
        for (int nt = 0; nt < 4; nt++) {
            const int col = bcol + wc * 32 + nt * 8 + 2 * tig;
            const float b0 = bias[col], b1 = bias[col + 1];
            float2 u, v;
            u.x = acc[mt][nt][0] + b0; u.y = acc[mt][nt][1] + b1;
            v.x = acc[mt][nt][2] + b0; v.y = acc[mt][nt][3] + b1;
            if (v0) *reinterpret_cast<float2*>(C + (size_t)r0 * N + col) = u;
            if (v1) *reinterpret_cast<float2*>(C + (size_t)r1 * N + col) = v;
        }
    }
}

// ---------------- weight prep A: 4 transposes -> bf16 ----------------
__global__ void wprepA_kernel(const float* __restrict__ Wv,  __nv_bfloat16* __restrict__ WvT,
                              const float* __restrict__ Wo,  __nv_bfloat16* __restrict__ WoT,
                              const float* __restrict__ W1,  __nv_bfloat16* __restrict__ W1T,
                              const float* __restrict__ W2,  __nv_bfloat16* __restrict__ W2T)
{
    __shared__ float t[32][33];
    const float* W; __nv_bfloat16* Wt; int K, N;
    switch (blockIdx.z) {
        case 0: W = Wv; Wt = WvT; K = DIM; N = DIM; break;
        case 1: W = Wo; Wt = WoT; K = DIM; N = DIM; break;
        case 2: W = W1; Wt = W1T; K = DIM; N = DFF; break;
        default:W = W2; Wt = W2T; K = DFF; N = DIM; break;
    }
    const int bx = blockIdx.x * 32;
    const int by = blockIdx.y * 32;
    if (bx >= N || by >= K) return;
    const int x = threadIdx.x, y = threadIdx.y;
    #pragma unroll
    for (int i = 0; i < 32; i += 8)
        t[y + i][x] = W[(size_t)(by + y + i) * N + bx + x];
    __syncthreads();
    #pragma unroll
    for (int i = 0; i < 32; i += 8)
        Wt[(size_t)(bx + y + i) * K + by + x] = __float2bfloat16(t[x][y + i]);
}

// ---------------- weight prep B: oa concat -> hi/lo bf16 ----------------
__global__ void wprepB_kernel(const float* __restrict__ Woff, const float* __restrict__ boff,
                              const float* __restrict__ Watt, const float* __restrict__ batt,
                              __nv_bfloat16* __restrict__ WoaTh, __nv_bfloat16* __restrict__ WoaTl,
                              float* __restrict__ boa)
{
    __shared__ float t[32][33];
    const int bx = blockIdx.x * 32;
    const int by = blockIdx.y * 32;
    const int x = threadIdx.x, y = threadIdx.y;
    const bool isAtt = (bx >= 256);
    const float* W = isAtt ? Watt : Woff;
    const int    nN = isAtt ? 128 : 256;
    const int    nb = isAtt ? bx - 256 : bx;
    #pragma unroll
    for (int i = 0; i < 32; i += 8)
        t[y + i][x] = W[(size_t)(by + y + i) * nN + nb + x];
    __syncthreads();
    #pragma unroll
    for (int i = 0; i < 32; i += 8) {
        float w = t[x][y + i];
        __nv_bfloat16 h = __float2bfloat16(w);
        size_t idx = (size_t)(bx + y + i) * DIM + by + x;
        WoaTh[idx] = h;
        WoaTl[idx] = __float2bfloat16(w - __bfloat162float(h));
    }
    if (blockIdx.y == 0 && y == 0) {
        int n = bx + x;
        boa[n] = (n < 256) ? boff[n] : batt[n - 256];
    }
}

// ---------------- MS-deform sampling v3 ----------------
__global__ void __launch_bounds__(128) msda_kernel(
    const __nv_bfloat16* __restrict__ value,
    const float* __restrict__ oa,
    const float* __restrict__ refpts,
    float* __restrict__ samp)
{
    const int nq   = blockIdx.x;
    const int wh   = threadIdx.x >> 5;
    const int lane = threadIdx.x & 31;
    const int g    = lane >> 4;
    const int j    = lane & 15;
    const int h    = wh * 2 + g;
    const int n    = nq / LQ;

    float logit = oa[(size_t)nq * NOA + 256 + wh * 32 + lane];
    float m = logit;
    #pragma unroll
    for (int o = 8; o > 0; o >>= 1) m = fmaxf(m, __shfl_xor_sync(0xffffffffu, m, o, 16));
    float e = __expf(logit - m);
    float s = e;
    #pragma unroll
    for (int o = 8; o > 0; o >>= 1) s += __shfl_xor_sync(0xffffffffu, s, o, 16);
    const float wi = e / s;

    const float2 offv = *reinterpret_cast<const float2*>(oa + (size_t)nq * NOA + wh * 64 + 2 * lane);
    float2 refv = make_float2(0.f, 0.f);
    if (lane < 4) refv = *reinterpret_cast<const float2*>(refpts + (size_t)nq * 8 + 2 * lane);
    const int l = j >> 2;
    const float refx = __shfl_sync(0xffffffffu, refv.x, l);
    const float refy = __shfl_sync(0xffffffffu, refv.y, l);

    const int Hl = c_H[l], Wl = c_W[l], st = c_S[l];
    const float x = refx * (float)Wl + offv.x - 0.5f;
    const float y = refy * (float)Hl + offv.y - 0.5f;
    const float x0f = floorf(x), y0f = floorf(y);
    const float fx = x - x0f, fy = y - y0f;
    const int x0 = (int)x0f, y0 = (int)y0f;
    const int x1 = x0 + 1,   y1 = y0 + 1;
    const float vx0 = (x0 >= 0 && x0 < Wl) ? 1.f : 0.f;
    const float vx1 = (x1 >= 0 && x1 < Wl) ? 1.f : 0.f;
    const float vy0 = (y0 >= 0 && y0 < Hl) ? 1.f : 0.f;
    const float vy1 = (y1 >= 0 && y1 < Hl) ? 1.f : 0.f;
    const int xc0 = min(max(x0, 0), Wl - 1), xc1 = min(max(x1, 0), Wl - 1);
    const int yc0 = min(max(y0, 0), Hl - 1), yc1 = min(max(y1, 0), Hl - 1);
    const uint32_t o00 = (uint32_t)(st + yc0 * Wl + xc0) * 512u;
    const uint32_t o01 = (uint32_t)(st + yc0 * Wl + xc1) * 512u;
    const uint32_t o10 = (uint32_t)(st + yc1 * Wl + xc0) * 512u;
    const uint32_t o11 = (uint32_t)(st + yc1 * Wl + xc1) * 512u;
    const float w00 = (1.f - fx) * (1.f - fy) * vx0 * vy0 * wi;
    const float w01 = fx * (1.f - fy) * vx1 * vy0 * wi;
    const float w10 = (1.f - fx) * fy * vx0 * vy1 * wi;
    const float w11 = fx * fy * vx1 * vy1 * wi;

    const char* vb = reinterpret_cast<const char*>(
        value + ((size_t)n * LIN * HEADS + h) * HD + 2 * j);

    float2 acc = make_float2(0.f, 0.f);
    #pragma unroll
    for (int i = 0; i < 16; i++) {
        const int src = g * 16 + i;
        const uint32_t q00 = __shfl_sync(0xffffffffu, o00, src);
        const uint32_t q01 = __shfl_sync(0xffffffffu, o01, src);
        const uint32_t q10 = __shfl_sync(0xffffffffu, o10, src);
        const uint32_t q11 = __shfl_sync(0xffffffffu, o11, src);
        const float u00 = __shfl_sync(0xffffffffu, w00, src);
        const float u01 = __shfl_sync(0xffffffffu, w01, src);
        const float u10 = __shfl_sync(0xffffffffu, w10, src);
        const float u11 = __shfl_sync(0xffffffffu, w11, src);

        float2 v00 = __bfloat1622float2(*reinterpret_cast<const __nv_bfloat162*>(vb + q00));
        float2 v01 = __bfloat1622float2(*reinterpret_cast<const __nv_bfloat162*>(vb + q01));
        float2 v10 = __bfloat1622float2(*reinterpret_cast<const __nv_bfloat162*>(vb + q10));
        float2 v11 = __bfloat1622float2(*reinterpret_cast<const __nv_bfloat162*>(vb + q11));

        acc.x += u00 * v00.x + u01 * v01.x + u10 * v10.x + u11 * v11.x;
        acc.y += u00 * v00.y + u01 * v01.y + u10 * v10.y + u11 * v11.y;
    }
    *reinterpret_cast<float2*>(samp + (size_t)nq * 256 + h * 32 + 2 * j) = acc;
}

// ---------------- fused residual + LayerNorm (warp per row) ----------------
__global__ void ln_kernel(const float* __restrict__ a, const float* __restrict__ b,
                          const float* __restrict__ g, const float* __restrict__ be,
                          float* __restrict__ out)
{
    const int row  = blockIdx.x * 8 + (threadIdx.x >> 5);
    const int lane = threadIdx.x & 31;
    const size_t base = (size_t)row * 256;

    float4 a0 = *reinterpret_cast<const float4*>(a + base + lane * 4);
    float4 a1 = *reinterpret_cast<const float4*>(a + base + 128 + lane * 4);
    float4 b0 = *reinterpret_cast<const float4*>(b + base + lane * 4);
    float4 b1 = *reinterpret_cast<const float4*>(b + base + 128 + lane * 4);
    float x0 = a0.x + b0.x, x1 = a0.y + b0.y, x2 = a0.z + b0.z, x3 = a0.w + b0.w;
    float x4 = a1.x + b1.x, x5 = a1.y + b1.y, x6 = a1.z + b1.z, x7 = a1.w + b1.w;

    float s  = x0 + x1 + x2 + x3 + x4 + x5 + x6 + x7;
    float s2 = x0*x0 + x1*x1 + x2*x2 + x3*x3 + x4*x4 + x5*x5 + x6*x6 + x7*x7;
    #pragma unroll
    for (int o = 16; o > 0; o >>= 1) {
        s  += __shfl_xor_sync(0xffffffffu, s,  o);
        s2 += __shfl_xor_sync(0xffffffffu, s2, o);
    }
    const float mean = s * (1.f / 256.f);
    const float rstd = rsqrtf(s2 * (1.f / 256.f) - mean * mean + 1e-5f);

    float4 g0 = *reinterpret_cast<const float4*>(g + lane * 4);
    float4 g1 = *reinterpret_cast<const float4*>(g + 128 + lane * 4);
    float4 e0 = *reinterpret_cast<const float4*>(be + lane * 4);
    float4 e1 = *reinterpret_cast<const float4*>(be + 128 + lane * 4);

    float4 o0, o1;
    o0.x = (x0 - mean) * rstd * g0.x + e0.x;
    o0.y = (x1 - mean) * rstd * g0.y + e0.y;
    o0.z = (x2 - mean) * rstd * g0.z + e0.z;
    o0.w = (x3 - mean) * rstd * g0.w + e0.w;
    o1.x = (x4 - mean) * rstd * g1.x + e1.x;
    o1.y = (x5 - mean) * rstd * g1.y + e1.y;
    o1.z = (x6 - mean) * rstd * g1.z + e1.z;
    o1.w = (x7 - mean) * rstd * g1.w + e1.w;
    *reinterpret_cast<float4*>(out + base + lane * 4)       = o0;
    *reinterpret_cast<float4*>(out + base + 128 + lane * 4) = o1;
}

// ---------------- launch ----------------
extern "C" void kernel_launch(void* const* d_in, const int* in_sizes, int n_in,
                              void* d_out, int out_size)
{
    const float* pre_tgt  = (const float*)d_in[0];
    const float* pre_qpos = (const float*)d_in[1];
    const float* src      = (const float*)d_in[2];
    const float* ref_pts  = (const float*)d_in[3];
    const unsigned char* mask = (const unsigned char*)d_in[4];
    const float* W_value = (const float*)d_in[7];
    const float* b_value = (const float*)d_in[8];
    const float* W_off   = (const float*)d_in[9];
    const float* b_off   = (const float*)d_in[10];
    const float* W_attn  = (const float*)d_in[11];
    const float* b_attn  = (const float*)d_in[12];
    const float* W_out   = (const float*)d_in[13];
    const float* b_out   = (const float*)d_in[14];
    const float* g1      = (const float*)d_in[15];
    const float* be1     = (const float*)d_in[16];
    const float* W1      = (const float*)d_in[17];
    const float* b1      = (const float*)d_in[18];
    const float* W2      = (const float*)d_in[19];
    const float* b2      = (const float*)d_in[20];
    const float* g3      = (const float*)d_in[21];
    const float* be3     = (const float*)d_in[22];

    __nv_bfloat16 *p_value, *p_WvTb, *p_WoutTb, *p_W1Tb, *p_W2Tb, *p_WoaTh, *p_WoaTl;
    float *p_oa, *p_samp, *p_ms, *p_tgt, *p_ffh, *p_ff, *p_boa;
    cudaGetSymbolAddress((void**)&p_value, g_value);
    cudaGetSymbolAddress((void**)&p_oa,    g_oa);
    cudaGetSymbolAddress((void**)&p_samp,  g_samp);
    cudaGetSymbolAddress((void**)&p_ms,    g_ms);
    cudaGetSymbolAddress((void**)&p_tgt,   g_tgt);
    cudaGetSymbolAddress((void**)&p_ffh,   g_ffh);
    cudaGetSymbolAddress((void**)&p_ff,    g_ff);
    cudaGetSymbolAddress((void**)&p_WvTb,  g_WvTb);
    cudaGetSymbolAddress((void**)&p_WoutTb,g_WoutTb);
    cudaGetSymbolAddress((void**)&p_W1Tb,  g_W1Tb);
    cudaGetSymbolAddress((void**)&p_W2Tb,  g_W2Tb);
    cudaGetSymbolAddress((void**)&p_WoaTh, g_WoaTh);
    cudaGetSymbolAddress((void**)&p_WoaTl, g_WoaTl);
    cudaGetSymbolAddress((void**)&p_boa,   g_boa);

    const int MV = NB * LIN;   // 174080
    dim3 tb(32, 8);

    // 1-2. weight prep
    wprepA_kernel<<<dim3(16, 16, 4), tb>>>(W_value, p_WvTb, W_out, p_WoutTb,
                                           W1, p_W1Tb, W2, p_W2Tb);
    wprepB_kernel<<<dim3(12, 8), tb>>>(W_off, b_off, W_attn, b_attn,
                                       p_WoaTh, p_WoaTl, p_boa);
    // 3. oa = (pre_tgt + pre_qpos) @ [Woff|Wattn] + bias   (bf16x3)
    mma_gemm_x3<<<dim3(NOA / 128, (NQ + 127) / 128), 256>>>(
        pre_tgt, pre_qpos, p_WoaTh, p_WoaTl, p_boa, p_oa, NQ, NOA, DIM);
    // 4. value = mask(src @ Wv + bv) -> bf16   (v7: BM=64, 3 CTAs/SM; launch #4)
    mma_gemm_v7<0, true, 1><<<dim3(2, MV / 64), 256>>>(
        src, p_WvTb, b_value, p_value, MV, DIM, DIM, mask);
    // 5. sampling
    msda_kernel<<<NQ, 128>>>(p_value, p_oa, ref_pts, p_samp);
    // 6. ms = samp @ Wout + bout
    mma_gemm_v7<0, false, 0><<<dim3(2, NQ / 64), 256>>>(
        p_samp, p_WoutTb, b_out, p_ms, NQ, DIM, DIM, nullptr);
    // 7. tgt = LN(pre_tgt + ms)
    ln_kernel<<<NQ / 8, 256>>>(pre_tgt, p_ms, g1, be1, p_tgt);
    // 8. ffh = relu(tgt @ W1 + b1)
    mma_gemm_v7<1, false, 0><<<dim3(4, NQ / 64), 256>>>(
        p_tgt, p_W1Tb, b1, p_ffh, NQ, DFF, DIM, nullptr);
    // 9. ff = ffh @ W2 + b2
    mma_gemm_v7<0, false, 0><<<dim3(2, NQ / 64), 256>>>(
        p_ffh, p_W2Tb, b2, p_ff, NQ, DIM, DFF, nullptr);
    // 10. out = LN(tgt + ff)
    ln_kernel<<<NQ / 8, 256>>>(p_tgt, p_ff, g3, be3, (float*)d_out);
}

// round 14
// speedup vs baseline: 1.0758x; 1.0758x over previous
#include <cuda_runtime.h>
#include <cuda_bf16.h>
#include <cstdint>

// ---------------- Problem constants ----------------
#define NB   8
#define LQ   1000
#define NQ   (NB*LQ)
#define DIM  256
#define HEADS 8
#define HD   32
#define LIN  21760
#define DFF  512
#define NOA  384

__device__ __constant__ int c_H[4]  = {128, 64, 32, 16};
__device__ __constant__ int c_W[4]  = {128, 64, 32, 16};
__device__ __constant__ int c_S[4]  = {0, 16384, 20480, 21504};

// ---------------- Scratch ----------------
__device__ __nv_bfloat16 g_value[(size_t)LIN * NB * DIM];
__device__ float g_oa   [(size_t)NQ * NOA];
__device__ float g_samp [(size_t)NQ * DIM];
__device__ float g_ms   [(size_t)NQ * DIM];
__device__ float g_tgt  [(size_t)NQ * DIM];
__device__ float g_ffh  [(size_t)NQ * DFF];
__device__ float g_ff   [(size_t)NQ * DIM];
__device__ __nv_bfloat16 g_WvTb [DIM * DIM];
__device__ __nv_bfloat16 g_WoutTb[DIM * DIM];
__device__ __nv_bfloat16 g_W1Tb [DFF * DIM];
__device__ __nv_bfloat16 g_W2Tb [DIM * DFF];
__device__ __nv_bfloat16 g_WoaTh[NOA * DIM];
__device__ __nv_bfloat16 g_WoaTl[NOA * DIM];
__device__ float g_boa  [NOA];

// ---------------- helpers ----------------
__device__ __forceinline__ void mma_bf16(float* d, const uint32_t* a, const uint32_t* b) {
    asm volatile(
        "mma.sync.aligned.m16n8k16.row.col.f32.bf16.bf16.f32 "
        "{%0,%1,%2,%3}, {%4,%5,%6,%7}, {%8,%9}, {%0,%1,%2,%3};"
        : "+f"(d[0]), "+f"(d[1]), "+f"(d[2]), "+f"(d[3])
        : "r"(a[0]), "r"(a[1]), "r"(a[2]), "r"(a[3]), "r"(b[0]), "r"(b[1]));
}
__device__ __forceinline__ void ldmx4(uint32_t* r, uint32_t addr) {
    asm volatile("ldmatrix.sync.aligned.m8n8.x4.shared.b16 {%0,%1,%2,%3}, [%4];"
        : "=r"(r[0]), "=r"(r[1]), "=r"(r[2]), "=r"(r[3]) : "r"(addr));
}
__device__ __forceinline__ uint32_t packbf(float lo, float hi) {
    __nv_bfloat162 h = __floats2bfloat162_rn(lo, hi);
    return *reinterpret_cast<uint32_t*>(&h);
}
__device__ __forceinline__ void cpa16(uint32_t dst, const void* src) {
    asm volatile("cp.async.cg.shared.global [%0], [%1], 16;" :: "r"(dst), "l"(src) : "memory");
}
#define CPA_COMMIT() asm volatile("cp.async.commit_group;" ::: "memory")
#define CPA_WAIT0()  asm volatile("cp.async.wait_group 0;"  ::: "memory")
#define SW64(o) ((uint32_t)(o) ^ (((uint32_t)(o) >> 3) & 0x30u))

// ================= bf16 mma GEMM v6 (BM=128 fixed — best measured config) =========
template<int ACT, bool MASK, int OUT>
__global__ void __launch_bounds__(256, 2) mma_gemm_v6(
    const float* __restrict__ A, const __nv_bfloat16* __restrict__ Bb,
    const float* __restrict__ bias, void* __restrict__ Cv,
    int M, int N, int K, const unsigned char* __restrict__ rowmask)
{
    __shared__ __align__(128) __nv_bfloat16 As[2][128 * 32];
    __shared__ __align__(128) __nv_bfloat16 Bs[2][128 * 32];

    const int tid  = threadIdx.x;
    const int lane = tid & 31;
    const int wid  = tid >> 5;
    const int wr   = wid & 1;
    const int wc   = wid >> 1;
    const int gid  = lane >> 2;
    const int tig  = lane & 3;
    const int brow = blockIdx.y * 128;
    const int bcol = blockIdx.x * 128;

    const int r_st = tid >> 3;
    const int kq   = (tid & 7) * 4;
    const int sts_col = (tid & 7) * 8;
    const int b_row_cp = tid >> 2;
    const int b_cg     = (tid & 3);

    float acc[4][4][4];
    #pragma unroll
    for (int i = 0; i < 4; i++)
        #pragma unroll
        for (int j = 0; j < 4; j++)
            #pragma unroll
            for (int l = 0; l < 4; l++) acc[i][j][l] = 0.f;

    const uint32_t asb = (uint32_t)__cvta_generic_to_shared(&As[0][0]);
    const uint32_t bsb = (uint32_t)__cvta_generic_to_shared(&Bs[0][0]);
    const uint32_t bufoff = 128 * 32 * 2;

    const int a_row = (lane & 7) + ((lane >> 3) & 1) * 8;
    const int a_col = (lane >> 4) * 16;
    const int b_row = (lane & 7) + ((lane >> 4) & 1) * 8;
    const int b_col = ((lane >> 3) & 1) * 16;

    uint2 pa[4];

    #define LD_A(kc) do {                                                               \
        _Pragma("unroll")                                                               \
        for (int i = 0; i < 4; i++) {                                                   \
            int gr = brow + r_st + 32 * i; if (gr >= M) gr = M - 1;                     \
            float4 v = *reinterpret_cast<const float4*>(A + (size_t)gr * K + (kc) + kq);\
            pa[i].x = packbf(v.x, v.y); pa[i].y = packbf(v.z, v.w);                     \
        }                                                                               \
    } while (0)

    #define ST_A(buf) do {                                                              \
        char* sa = reinterpret_cast<char*>(&As[buf][0]);                                \
        _Pragma("unroll")                                                               \
        for (int i = 0; i < 4; i++)                                                     \
            *reinterpret_cast<uint2*>(sa + SW64((r_st + 32 * i) * 64 + sts_col)) = pa[i];\
    } while (0)

    #define CPA_B(kc, buf) do {                                                         \
        _Pragma("unroll")                                                               \
        for (int j = 0; j < 2; j++) {                                                   \
            int row = b_row_cp + 64 * j;                                                \
            cpa16(bsb + (buf) * bufoff + SW64(row * 64 + b_cg * 16),                    \
                  Bb + (size_t)(bcol + row) * K + (kc) + b_cg * 8);                     \
        }                                                                               \
    } while (0)

    const int KT = K >> 5;
    CPA_B(0, 0);
    CPA_COMMIT();
    LD_A(0);
    ST_A(0);
    CPA_WAIT0();
    __syncthreads();

    for (int kt = 0; kt < KT; kt++) {
        const int buf = kt & 1;
        if (kt + 1 < KT) {
            CPA_B((kt + 1) * 32, buf ^ 1);
            CPA_COMMIT();
            LD_A((kt + 1) * 32);
        }

        const uint32_t ab = asb + buf * bufoff;
        const uint32_t bb = bsb + buf * bufoff;
        #pragma unroll
        for (int ks = 0; ks < 2; ks++) {
            uint32_t af[4][4], bfq[2][4];
            #pragma unroll
            for (int mt = 0; mt < 4; mt++)
                ldmx4(af[mt], ab + SW64((wr * 64 + mt * 16 + a_row) * 64 + a_col + ks * 32));
            #pragma unroll
            for (int p = 0; p < 2; p++)
                ldmx4(bfq[p], bb + SW64((wc * 32 + p * 16 + b_row) * 64 + b_col + ks * 32));
            #pragma unroll
            for (int mt = 0; mt < 4; mt++)
                #pragma unroll
                for (int nt = 0; nt < 4; nt++)
                    mma_bf16(acc[mt][nt], af[mt], &bfq[nt >> 1][(nt & 1) * 2]);
        }

        if (kt + 1 < KT) {
            ST_A(buf ^ 1);
            CPA_WAIT0();
            __syncthreads();
        }
    }
    #undef LD_A
    #undef ST_A
    #undef CPA_B

    float* Cf = (float*)Cv;
    __nv_bfloat16* Cb = (__nv_bfloat16*)Cv;

    #pragma unroll
    for (int mt = 0; mt < 4; mt++) {
        const int r0 = brow + wr * 64 + mt * 16 + gid;
        const int r1 = r0 + 8;
        const bool v0 = r0 < M, v1 = r1 < M;
        bool z0 = false, z1 = false;
        if (MASK) {
            if (v0) z0 = (rowmask[r0] != 0);
            if (v1) z1 = (rowmask[r1] != 0);
        }
        #pragma unroll
        for (int nt = 0; nt < 4; nt++) {
            const int col = bcol + wc * 32 + nt * 8 + 2 * tig;
            const float b0 = bias[col], b1 = bias[col + 1];
            float2 u, v;
            u.x = acc[mt][nt][0] + b0; u.y = acc[mt][nt][1] + b1;
            v.x = acc[mt][nt][2] + b0; v.y = acc[mt][nt][3] + b1;
            if (ACT == 1) {
                u.x = fmaxf(u.x, 0.f); u.y = fmaxf(u.y, 0.f);
                v.x = fmaxf(v.x, 0.f); v.y = fmaxf(v.y, 0.f);
            }
            if (MASK) {
                if (z0) { u.x = 0.f; u.y = 0.f; }
                if (z1) { v.x = 0.f; v.y = 0.f; }
            }
            if (OUT == 0) {
                if (v0) *reinterpret_cast<float2*>(Cf + (size_t)r0 * N + col) = u;
                if (v1) *reinterpret_cast<float2*>(Cf + (size_t)r1 * N + col) = v;
            } else {
                __nv_bfloat162 hu = __floats2bfloat162_rn(u.x, u.y);
                __nv_bfloat162 hv = __floats2bfloat162_rn(v.x, v.y);
                if (v0) *reinterpret_cast<__nv_bfloat162*>(Cb + (size_t)r0 * N + col) = hu;
                if (v1) *reinterpret_cast<__nv_bfloat162*>(Cb + (size_t)r1 * N + col) = hv;
            }
        }
    }
}

// ================= bf16x3 GEMM (oa): ~fp32 precision =================
__global__ void __launch_bounds__(256, 2) mma_gemm_x3(
    const float* __restrict__ A, const float* __restrict__ A2,
    const __nv_bfloat16* __restrict__ Bh, const __nv_bfloat16* __restrict__ Bl,
    const float* __restrict__ bias, float* __restrict__ C,
    int M, int N, int K)
{
    __shared__ __align__(128) __nv_bfloat16 Ahs[128 * 32];
    __shared__ __align__(128) __nv_bfloat16 Als[128 * 32];
    __shared__ __align__(128) __nv_bfloat16 Bhs[128 * 32];
    __shared__ __align__(128) __nv_bfloat16 Bls[128 * 32];

    const int tid  = threadIdx.x;
    const int lane = tid & 31;
    const int wid  = tid >> 5;
    const int wr   = wid & 1;
    const int wc   = wid >> 1;
    const int gid  = lane >> 2;
    const int tig  = lane & 3;
    const int brow = blockIdx.y * 128;
    const int bcol = blockIdx.x * 128;

    const int r_st = tid >> 3;
    const int kq   = (tid & 7) * 4;
    const int sts_col = (tid & 7) * 8;
    const int b_row_cp = tid >> 2;
    const int b_cg     = (tid & 3);

    float acc[4][4][4];
    #pragma unroll
    for (int i = 0; i < 4; i++)
        #pragma unroll
        for (int j = 0; j < 4; j++)
            #pragma unroll
            for (int l = 0; l < 4; l++) acc[i][j][l] = 0.f;

    const uint32_t ahb = (uint32_t)__cvta_generic_to_shared(&Ahs[0]);
    const uint32_t alb = (uint32_t)__cvta_generic_to_shared(&Als[0]);
    const uint32_t bhb = (uint32_t)__cvta_generic_to_shared(&Bhs[0]);
    const uint32_t blb = (uint32_t)__cvta_generic_to_shared(&Bls[0]);

    const int a_row = (lane & 7) + ((lane >> 3) & 1) * 8;
    const int a_col = (lane >> 4) * 16;
    const int b_row = (lane & 7) + ((lane >> 4) & 1) * 8;
    const int b_col = ((lane >> 3) & 1) * 16;

    uint2 pah[4], pal[4];

    #define LD_AX(kc) do {                                                              \
        _Pragma("unroll")                                                               \
        for (int i = 0; i < 4; i++) {                                                   \
            int gr = brow + r_st + 32 * i; if (gr >= M) gr = M - 1;                     \
            float4 v  = *reinterpret_cast<const float4*>(A  + (size_t)gr * K + (kc) + kq);\
            float4 v2 = *reinterpret_cast<const float4*>(A2 + (size_t)gr * K + (kc) + kq);\
            v.x += v2.x; v.y += v2.y; v.z += v2.z; v.w += v2.w;                         \
            __nv_bfloat162 h0 = __floats2bfloat162_rn(v.x, v.y);                        \
            __nv_bfloat162 h1 = __floats2bfloat162_rn(v.z, v.w);                        \
            float2 f0 = __bfloat1622float2(h0);                                         \
            float2 f1 = __bfloat1622float2(h1);                                         \
            pah[i].x = *reinterpret_cast<uint32_t*>(&h0);                               \
            pah[i].y = *reinterpret_cast<uint32_t*>(&h1);                               \
            pal[i].x = packbf(v.x - f0.x, v.y - f0.y);                                  \
            pal[i].y = packbf(v.z - f1.x, v.w - f1.y);                                  \
        }                                                                               \
    } while (0)

    #define ST_AX() do {                                                                \
        char* sh = reinterpret_cast<char*>(&Ahs[0]);                                    \
        char* sl = reinterpret_cast<char*>(&Als[0]);                                    \
        _Pragma("unroll")                                                               \
        for (int i = 0; i < 4; i++) {                                                   \
            uint32_t o = SW64((r_st + 32 * i) * 64 + sts_col);                          \
            *reinterpret_cast<uint2*>(sh + o) = pah[i];                                 \
            *reinterpret_cast<uint2*>(sl + o) = pal[i];                                 \
        }                                                                               \
    } while (0)

    #define CPA_BX(kc) do {                                                             \
        _Pragma("unroll")                                                               \
        for (int j = 0; j < 2; j++) {                                                   \
            int row = b_row_cp + 64 * j;                                                \
            uint32_t o = SW64(row * 64 + b_cg * 16);                                    \
            size_t gsrc = (size_t)(bcol + row) * K + (kc) + b_cg * 8;                   \
            cpa16(bhb + o, Bh + gsrc);                                                  \
            cpa16(blb + o, Bl + gsrc);                                                  \
        }                                                                               \
    } while (0)

    const int KT = K >> 5;
    LD_AX(0);
    for (int kt = 0; kt < KT; kt++) {
        if (kt) __syncthreads();
        ST_AX();
        CPA_BX(kt * 32);
        CPA_COMMIT();
        if (kt + 1 < KT) LD_AX((kt + 1) * 32);
        CPA_WAIT0();
        __syncthreads();

        #pragma unroll
        for (int ks = 0; ks < 2; ks++) {
            uint32_t afh[4][4], bfh[2][4];
            #pragma unroll
            for (int mt = 0; mt < 4; mt++)
                ldmx4(afh[mt], ahb + SW64((wr * 64 + mt * 16 + a_row) * 64 + a_col + ks * 32));
            #pragma unroll
            for (int p = 0; p < 2; p++)
                ldmx4(bfh[p], bhb + SW64((wc * 32 + p * 16 + b_row) * 64 + b_col + ks * 32));
            #pragma unroll
            for (int mt = 0; mt < 4; mt++)
                #pragma unroll
                for (int nt = 0; nt < 4; nt++)
                    mma_bf16(acc[mt][nt], afh[mt], &bfh[nt >> 1][(nt & 1) * 2]);

            {
                uint32_t bfl[2][4];
                #pragma unroll
                for (int p = 0; p < 2; p++)
                    ldmx4(bfl[p], blb + SW64((wc * 32 + p * 16 + b_row) * 64 + b_col + ks * 32));
                #pragma unroll
                for (int mt = 0; mt < 4; mt++)
                    #pragma unroll
                    for (int nt = 0; nt < 4; nt++)
                        mma_bf16(acc[mt][nt], afh[mt], &bfl[nt >> 1][(nt & 1) * 2]);
            }
            {
                uint32_t afl[4][4];
                #pragma unroll
                for (int mt = 0; mt < 4; mt++)
                    ldmx4(afl[mt], alb + SW64((wr * 64 + mt * 16 + a_row) * 64 + a_col + ks * 32));
                #pragma unroll
                for (int mt = 0; mt < 4; mt++)
                    #pragma unroll
                    for (int nt = 0; nt < 4; nt++)
                        mma_bf16(acc[mt][nt], afl[mt], &bfh[nt >> 1][(nt & 1) * 2]);
            }
        }
    }
    #undef LD_AX
    #undef ST_AX
    #undef CPA_BX

    #pragma unroll
    for (int mt = 0; mt < 4; mt++) {
        const int r0 = brow + wr * 64 + mt * 16 + gid;
        const int r1 = r0 + 8;
        const bool v0 = r0 < M, v1 = r1 < M;
        #pragma unroll
        for (int nt = 0; nt < 4; nt++) {
            const int col = bcol + wc * 32 + nt * 8 + 2 * tig;
            const float b0 = bias[col], b1 = bias[col + 1];
            float2 u, v;
            u.x = acc[mt][nt][0] + b0; u.y = acc[mt][nt][1] + b1;
            v.x = acc[mt][nt][2] + b0; v.y = acc[mt][nt][3] + b1;
            if (v0) *reinterpret_cast<float2*>(C + (size_t)r0 * N + col) = u;
            if (v1) *reinterpret_cast<float2*>(C + (size_t)r1 * N + col) = v;
        }
    }
}

// ---------------- unified weight prep: z=0..3 transpose->bf16, z=4 oa concat hi/lo --
__global__ void wprep_kernel(const float* __restrict__ Wv,  __nv_bfloat16* __restrict__ WvT,
                             const float* __restrict__ Wo,  __nv_bfloat16* __restrict__ WoT,
                             const float* __restrict__ W1,  __nv_bfloat16* __restrict__ W1T,
                             const float* __restrict__ W2,  __nv_bfloat16* __restrict__ W2T,
                             const float* __restrict__ Woff, const float* __restrict__ boff,
                             const float* __restrict__ Watt, const float* __restrict__ batt,
                             __nv_bfloat16* __restrict__ WoaTh, __nv_bfloat16* __restrict__ WoaTl,
                             float* __restrict__ boa)
{
    __shared__ float t[32][33];
    const int x = threadIdx.x, y = threadIdx.y;
    const int z = blockIdx.z;

    if (z == 4) {
        const int bx = blockIdx.x * 32;
        const int by = blockIdx.y * 32;
        if (bx >= NOA || by >= DIM) return;
        const bool isAtt = (bx >= 256);
        const float* W = isAtt ? Watt : Woff;
        const int    nN = isAtt ? 128 : 256;
        const int    nb = isAtt ? bx - 256 : bx;
        #pragma unroll
        for (int i = 0; i < 32; i += 8)
            t[y + i][x] = W[(size_t)(by + y + i) * nN + nb + x];
        __syncthreads();
        #pragma unroll
        for (int i = 0; i < 32; i += 8) {
            float w = t[x][y + i];
            __nv_bfloat16 h = __float2bfloat16(w);
            size_t idx = (size_t)(bx + y + i) * DIM + by + x;
            WoaTh[idx] = h;
            WoaTl[idx] = __float2bfloat16(w - __bfloat162float(h));
        }
        if (blockIdx.y == 0 && y == 0) {
            int n = bx + x;
            boa[n] = (n < 256) ? boff[n] : batt[n - 256];
        }
        return;
    }

    const float* W; __nv_bfloat16* Wt; int K, N;
    switch (z) {
        case 0: W = Wv; Wt = WvT; K = DIM; N = DIM; break;
        case 1: W = Wo; Wt = WoT; K = DIM; N = DIM; break;
        case 2: W = W1; Wt = W1T; K = DIM; N = DFF; break;
        default:W = W2; Wt = W2T; K = DFF; N = DIM; break;
    }
    const int bx = blockIdx.x * 32;
    const int by = blockIdx.y * 32;
    if (bx >= N || by >= K) return;
    #pragma unroll
    for (int i = 0; i < 32; i += 8)
        t[y + i][x] = W[(size_t)(by + y + i) * N + bx + x];
    __syncthreads();
    #pragma unroll
    for (int i = 0; i < 32; i += 8)
        Wt[(size_t)(bx + y + i) * K + by + x] = __float2bfloat16(t[x][y + i]);
}

// ---------------- MS-deform sampling v4: warp = 4 heads, uint2 gathers -----------
// block = 64 threads (2 warps), grid = NQ. warp w covers heads 4w..4w+3.
// lane = g*8 + ci: g = head-in-quad, ci = channel QUAD (channels 4ci..4ci+3).
// Each lane OWNS points ci and ci+8 of head (4w+g) for precompute.
__device__ __forceinline__ void msda_corners(
    int l, float2 off, float refx, float refy, float wi,
    uint32_t* q, float* u)
{
    const int Hl = c_H[l], Wl = c_W[l], st = c_S[l];
    const float x = refx * (float)Wl + off.x - 0.5f;
    const float y = refy * (float)Hl + off.y - 0.5f;
    const float x0f = floorf(x), y0f = floorf(y);
    const float fx = x - x0f, fy = y - y0f;
    const int x0 = (int)x0f, y0 = (int)y0f;
    const int x1 = x0 + 1,   y1 = y0 + 1;
    const float vx0 = (x0 >= 0 && x0 < Wl) ? 1.f : 0.f;
    const float vx1 = (x1 >= 0 && x1 < Wl) ? 1.f : 0.f;
    const float vy0 = (y0 >= 0 && y0 < Hl) ? 1.f : 0.f;
    const float vy1 = (y1 >= 0 && y1 < Hl) ? 1.f : 0.f;
    const int xc0 = min(max(x0, 0), Wl - 1), xc1 = min(max(x1, 0), Wl - 1);
    const int yc0 = min(max(y0, 0), Hl - 1), yc1 = min(max(y1, 0), Hl - 1);
    q[0] = (uint32_t)(st + yc0 * Wl + xc0) * 512u;
    q[1] = (uint32_t)(st + yc0 * Wl + xc1) * 512u;
    q[2] = (uint32_t)(st + yc1 * Wl + xc0) * 512u;
    q[3] = (uint32_t)(st + yc1 * Wl + xc1) * 512u;
    u[0] = (1.f - fx) * (1.f - fy) * vx0 * vy0 * wi;
    u[1] = fx * (1.f - fy) * vx1 * vy0 * wi;
    u[2] = (1.f - fx) * fy * vx0 * vy1 * wi;
    u[3] = fx * fy * vx1 * vy1 * wi;
}

__global__ void __launch_bounds__(64) msda_kernel(
    const __nv_bfloat16* __restrict__ value,
    const float* __restrict__ oa,
    const float* __restrict__ refpts,
    float* __restrict__ samp)
{
    const int nq   = blockIdx.x;
    const int w    = threadIdx.x >> 5;      // warp: heads 4w..4w+3
    const int lane = threadIdx.x & 31;
    const int g    = lane >> 3;             // head in quad
    const int ci   = lane & 7;              // channel quad
    const int h    = w * 4 + g;
    const int n    = nq / LQ;

    // --- softmax over this head's 16 logits (8 lanes x 2 each) ---
    const float lg0 = oa[(size_t)nq * NOA + 256 + h * 16 + ci];
    const float lg1 = oa[(size_t)nq * NOA + 256 + h * 16 + ci + 8];
    float m = fmaxf(lg0, lg1);
    #pragma unroll
    for (int o = 4; o > 0; o >>= 1) m = fmaxf(m, __shfl_xor_sync(0xffffffffu, m, o, 8));
    const float e0 = __expf(lg0 - m), e1 = __expf(lg1 - m);
    float s = e0 + e1;
    #pragma unroll
    for (int o = 4; o > 0; o >>= 1) s += __shfl_xor_sync(0xffffffffu, s, o, 8);
    const float wi0 = e0 / s, wi1 = e1 / s;

    // --- own points' offsets and refs ---
    const float2 off0 = *reinterpret_cast<const float2*>(oa + (size_t)nq * NOA + h * 32 + 2 * ci);
    const float2 off1 = *reinterpret_cast<const float2*>(oa + (size_t)nq * NOA + h * 32 + 2 * (ci + 8));
    float2 refv = make_float2(0.f, 0.f);
    if (lane < 4) refv = *reinterpret_cast<const float2*>(refpts + (size_t)nq * 8 + 2 * lane);
    const int l0 = ci >> 2;          // level of point ci (0 or 1)
    const int l1 = l0 + 2;           // level of point ci+8 (2 or 3)
    const float rx0 = __shfl_sync(0xffffffffu, refv.x, l0);
    const float ry0 = __shfl_sync(0xffffffffu, refv.y, l0);
    const float rx1 = __shfl_sync(0xffffffffu, refv.x, l1);
    const float ry1 = __shfl_sync(0xffffffffu, refv.y, l1);

    uint32_t q0[4], q1[4];
    float    u0[4], u1[4];
    msda_corners(l0, off0, rx0, ry0, wi0, q0, u0);
    msda_corners(l1, off1, rx1, ry1, wi1, q1, u1);

    const char* vb = reinterpret_cast<const char*>(
        value + ((size_t)n * LIN * HEADS + h) * HD + 4 * ci);

    float4 acc = make_float4(0.f, 0.f, 0.f, 0.f);

    #define GATHER(QARR, UARR, I) do {                                                  \
        const int src = g * 8 + (I);                                                    \
        const uint32_t qa = __shfl_sync(0xffffffffu, (QARR)[0], src);                   \
        const uint32_t qb = __shfl_sync(0xffffffffu, (QARR)[1], src);                   \
        const uint32_t qc = __shfl_sync(0xffffffffu, (QARR)[2], src);                   \
        const uint32_t qd = __shfl_sync(0xffffffffu, (QARR)[3], src);                   \
        const float ua = __shfl_sync(0xffffffffu, (UARR)[0], src);                      \
        const float ub = __shfl_sync(0xffffffffu, (UARR)[1], src);                      \
        const float uc = __shfl_sync(0xffffffffu, (UARR)[2], src);                      \
        const float ud = __shfl_sync(0xffffffffu, (UARR)[3], src);                      \
        const uint2 va = *reinterpret_cast<const uint2*>(vb + qa);                      \
        const uint2 vvb = *reinterpret_cast<const uint2*>(vb + qb);                     \
        const uint2 vc = *reinterpret_cast<const uint2*>(vb + qc);                      \
        const uint2 vd = *reinterpret_cast<const uint2*>(vb + qd);                      \
        float2 alo = __bfloat1622float2(*reinterpret_cast<const __nv_bfloat162*>(&va.x)); \
        float2 ahi = __bfloat1622float2(*reinterpret_cast<const __nv_bfloat162*>(&va.y)); \
        float2 blo = __bfloat1622float2(*reinterpret_cast<const __nv_bfloat162*>(&vvb.x)); \
        float2 bhi = __bfloat1622float2(*reinterpret_cast<const __nv_bfloat162*>(&vvb.y)); \
        float2 clo = __bfloat1622float2(*reinterpret_cast<const __nv_bfloat162*>(&vc.x)); \
        float2 chi = __bfloat1622float2(*reinterpret_cast<const __nv_bfloat162*>(&vc.y)); \
        float2 dlo = __bfloat1622float2(*reinterpret_cast<const __nv_bfloat162*>(&vd.x)); \
        float2 dhi = __bfloat1622float2(*reinterpret_cast<const __nv_bfloat162*>(&vd.y)); \
        acc.x += ua * alo.x + ub * blo.x + uc * clo.x + ud * dlo.x;                     \
        acc.y += ua * alo.y + ub * blo.y + uc * clo.y + ud * dlo.y;                     \
        acc.z += ua * ahi.x + ub * bhi.x + uc * chi.x + ud * dhi.x;                     \
        acc.w += ua * ahi.y + ub * bhi.y + uc * chi.y + ud * dhi.y;                     \
    } while (0)

    #pragma unroll
    for (int i = 0; i < 8; i++) GATHER(q0, u0, i);
    #pragma unroll
    for (int i = 0; i < 8; i++) GATHER(q1, u1, i);
    #undef GATHER

    *reinterpret_cast<float4*>(samp + (size_t)nq * 256 + h * 32 + 4 * ci) = acc;
}

// ---------------- fused residual + LayerNorm (warp per row) ----------------
__global__ void ln_kernel(const float* __restrict__ a, const float* __restrict__ b,
                          const float* __restrict__ g, const float* __restrict__ be,
                          float* __restrict__ out)
{
    const int row  = blockIdx.x * 8 + (threadIdx.x >> 5);
    const int lane = threadIdx.x & 31;
    const size_t base = (size_t)row * 256;

    float4 a0 = *reinterpret_cast<const float4*>(a + base + lane * 4);
    float4 a1 = *reinterpret_cast<const float4*>(a + base + 128 + lane * 4);
    float4 b0 = *reinterpret_cast<const float4*>(b + base + lane * 4);
    float4 b1 = *reinterpret_cast<const float4*>(b + base + 128 + lane * 4);
    float x0 = a0.x + b0.x, x1 = a0.y + b0.y, x2 = a0.z + b0.z, x3 = a0.w + b0.w;
    float x4 = a1.x + b1.x, x5 = a1.y + b1.y, x6 = a1.z + b1.z, x7 = a1.w + b1.w;

    float s  = x0 + x1 + x2 + x3 + x4 + x5 + x6 + x7;
    float s2 = x0*x0 + x1*x1 + x2*x2 + x3*x3 + x4*x4 + x5*x5 + x6*x6 + x7*x7;
    #pragma unroll
    for (int o = 16; o > 0; o >>= 1) {
        s  += __shfl_xor_sync(0xffffffffu, s,  o);
        s2 += __shfl_xor_sync(0xffffffffu, s2, o);
    }
    const float mean = s * (1.f / 256.f);
    const float rstd = rsqrtf(s2 * (1.f / 256.f) - mean * mean + 1e-5f);

    float4 g0 = *reinterpret_cast<const float4*>(g + lane * 4);
    float4 g1 = *reinterpret_cast<const float4*>(g + 128 + lane * 4);
    float4 e0 = *reinterpret_cast<const float4*>(be + lane * 4);
    float4 e1 = *reinterpret_cast<const float4*>(be + 128 + lane * 4);

    float4 o0, o1;
    o0.x = (x0 - mean) * rstd * g0.x + e0.x;
    o0.y = (x1 - mean) * rstd * g0.y + e0.y;
    o0.z = (x2 - mean) * rstd * g0.z + e0.z;
    o0.w = (x3 - mean) * rstd * g0.w + e0.w;
    o1.x = (x4 - mean) * rstd * g1.x + e1.x;
    o1.y = (x5 - mean) * rstd * g1.y + e1.y;
    o1.z = (x6 - mean) * rstd * g1.z + e1.z;
    o1.w = (x7 - mean) * rstd * g1.w + e1.w;
    *reinterpret_cast<float4*>(out + base + lane * 4)       = o0;
    *reinterpret_cast<float4*>(out + base + 128 + lane * 4) = o1;
}

// ---------------- launch ----------------
extern "C" void kernel_launch(void* const* d_in, const int* in_sizes, int n_in,
                              void* d_out, int out_size)
{
    const float* pre_tgt  = (const float*)d_in[0];
    const float* pre_qpos = (const float*)d_in[1];
    const float* src      = (const float*)d_in[2];
    const float* ref_pts  = (const float*)d_in[3];
    const unsigned char* mask = (const unsigned char*)d_in[4];
    const float* W_value = (const float*)d_in[7];
    const float* b_value = (const float*)d_in[8];
    const float* W_off   = (const float*)d_in[9];
    const float* b_off   = (const float*)d_in[10];
    const float* W_attn  = (const float*)d_in[11];
    const float* b_attn  = (const float*)d_in[12];
    const float* W_out   = (const float*)d_in[13];
    const float* b_out   = (const float*)d_in[14];
    const float* g1      = (const float*)d_in[15];
    const float* be1     = (const float*)d_in[16];
    const float* W1      = (const float*)d_in[17];
    const float* b1      = (const float*)d_in[18];
    const float* W2      = (const float*)d_in[19];
    const float* b2      = (const float*)d_in[20];
    const float* g3      = (const float*)d_in[21];
    const float* be3     = (const float*)d_in[22];

    __nv_bfloat16 *p_value, *p_WvTb, *p_WoutTb, *p_W1Tb, *p_W2Tb, *p_WoaTh, *p_WoaTl;
    float *p_oa, *p_samp, *p_ms, *p_tgt, *p_ffh, *p_ff, *p_boa;
    cudaGetSymbolAddress((void**)&p_value, g_value);
    cudaGetSymbolAddress((void**)&p_oa,    g_oa);
    cudaGetSymbolAddress((void**)&p_samp,  g_samp);
    cudaGetSymbolAddress((void**)&p_ms,    g_ms);
    cudaGetSymbolAddress((void**)&p_tgt,   g_tgt);
    cudaGetSymbolAddress((void**)&p_ffh,   g_ffh);
    cudaGetSymbolAddress((void**)&p_ff,    g_ff);
    cudaGetSymbolAddress((void**)&p_WvTb,  g_WvTb);
    cudaGetSymbolAddress((void**)&p_WoutTb,g_WoutTb);
    cudaGetSymbolAddress((void**)&p_W1Tb,  g_W1Tb);
    cudaGetSymbolAddress((void**)&p_W2Tb,  g_W2Tb);
    cudaGetSymbolAddress((void**)&p_WoaTh, g_WoaTh);
    cudaGetSymbolAddress((void**)&p_WoaTl, g_WoaTl);
    cudaGetSymbolAddress((void**)&p_boa,   g_boa);

    const int MV = NB * LIN;   // 174080
    dim3 tb(32, 8);

    // 1. unified weight prep
    wprep_kernel<<<dim3(16, 16, 5), tb>>>(W_value, p_WvTb, W_out, p_WoutTb,
                                          W1, p_W1Tb, W2, p_W2Tb,
                                          W_off, b_off, W_attn, b_attn,
                                          p_WoaTh, p_WoaTl, p_boa);
    // 2. value = mask(src @ Wv + bv) -> bf16   (v6 BM=128, best measured)
    mma_gemm_v6<0, true, 1><<<dim3(2, MV / 128), 256>>>(
        src, p_WvTb, b_value, p_value, MV, DIM, DIM, mask);
    // 3. oa = (pre_tgt + pre_qpos) @ [Woff|Wattn] + bias   (bf16x3)
    mma_gemm_x3<<<dim3(NOA / 128, (NQ + 127) / 128), 256>>>(
        pre_tgt, pre_qpos, p_WoaTh, p_WoaTl, p_boa, p_oa, NQ, NOA, DIM);
    // 4. sampling v4 (launch #4 -> profiled)
    msda_kernel<<<NQ, 64>>>(p_value, p_oa, ref_pts, p_samp);
    // 5. ms = samp @ Wout + bout
    mma_gemm_v6<0, false, 0><<<dim3(2, (NQ + 127) / 128), 256>>>(
        p_samp, p_WoutTb, b_out, p_ms, NQ, DIM, DIM, nullptr);
    // 6. tgt = LN(pre_tgt + ms)
    ln_kernel<<<NQ / 8, 256>>>(pre_tgt, p_ms, g1, be1, p_tgt);
    // 7. ffh = relu(tgt @ W1 + b1)
    mma_gemm_v6<1, false, 0><<<dim3(4, (NQ + 127) / 128), 256>>>(
        p_tgt, p_W1Tb, b1, p_ffh, NQ, DFF, DIM, nullptr);
    // 8. ff = ffh @ W2 + b2
    mma_gemm_v6<0, false, 0><<<dim3(2, (NQ + 127) / 128), 256>>>(
        p_ffh, p_W2Tb, b2, p_ff, NQ, DIM, DFF, nullptr);
    // 9. out = LN(tgt + ff)
    ln_kernel<<<NQ / 8, 256>>>(p_tgt, p_ff, g3, be3, (float*)d_out);
}

// round 15
// speedup vs baseline: 1.0864x; 1.0099x over previous
#include <cuda_runtime.h>
#include <cuda_bf16.h>
#include <cstdint>

// ---------------- Problem constants ----------------
#define NB   8
#define LQ   1000
#define NQ   (NB*LQ)
#define DIM  256
#define HEADS 8
#define HD   32
#define LIN  21760
#define DFF  512
#define NOA  384

__device__ __constant__ int c_H[4]  = {128, 64, 32, 16};
__device__ __constant__ int c_W[4]  = {128, 64, 32, 16};
__device__ __constant__ int c_S[4]  = {0, 16384, 20480, 21504};

// ---------------- Scratch ----------------
__device__ __nv_bfloat16 g_value[(size_t)LIN * NB * DIM];
__device__ float g_oa   [(size_t)NQ * NOA];
__device__ float g_samp [(size_t)NQ * DIM];
__device__ float g_ms   [(size_t)NQ * DIM];
__device__ float g_tgt  [(size_t)NQ * DIM];
__device__ float g_ffh  [(size_t)NQ * DFF];
__device__ float g_ff   [(size_t)NQ * DIM];
__device__ __nv_bfloat16 g_WvTb [DIM * DIM];
__device__ __nv_bfloat16 g_WoutTb[DIM * DIM];
__device__ __nv_bfloat16 g_W1Tb [DFF * DIM];
__device__ __nv_bfloat16 g_W2Tb [DIM * DFF];
__device__ __nv_bfloat16 g_WoaTh[NOA * DIM];
__device__ __nv_bfloat16 g_WoaTl[NOA * DIM];
__device__ float g_boa  [NOA];

// ---------------- helpers ----------------
__device__ __forceinline__ void mma_bf16(float* d, const uint32_t* a, const uint32_t* b) {
    asm volatile(
        "mma.sync.aligned.m16n8k16.row.col.f32.bf16.bf16.f32 "
        "{%0,%1,%2,%3}, {%4,%5,%6,%7}, {%8,%9}, {%0,%1,%2,%3};"
        : "+f"(d[0]), "+f"(d[1]), "+f"(d[2]), "+f"(d[3])
        : "r"(a[0]), "r"(a[1]), "r"(a[2]), "r"(a[3]), "r"(b[0]), "r"(b[1]));
}
__device__ __forceinline__ void ldmx4(uint32_t* r, uint32_t addr) {
    asm volatile("ldmatrix.sync.aligned.m8n8.x4.shared.b16 {%0,%1,%2,%3}, [%4];"
        : "=r"(r[0]), "=r"(r[1]), "=r"(r[2]), "=r"(r[3]) : "r"(addr));
}
__device__ __forceinline__ uint32_t packbf(float lo, float hi) {
    __nv_bfloat162 h = __floats2bfloat162_rn(lo, hi);
    return *reinterpret_cast<uint32_t*>(&h);
}
__device__ __forceinline__ void cpa16(uint32_t dst, const void* src) {
    asm volatile("cp.async.cg.shared.global [%0], [%1], 16;" :: "r"(dst), "l"(src) : "memory");
}
#define CPA_COMMIT() asm volatile("cp.async.commit_group;" ::: "memory")
#define CPA_WAIT0()  asm volatile("cp.async.wait_group 0;"  ::: "memory")
#define SW64(o) ((uint32_t)(o) ^ (((uint32_t)(o) >> 3) & 0x30u))

// ================= bf16 mma GEMM v6 (BM=128 — best measured config) =========
template<int ACT, bool MASK, int OUT>
__global__ void __launch_bounds__(256, 2) mma_gemm_v6(
    const float* __restrict__ A, const __nv_bfloat16* __restrict__ Bb,
    const float* __restrict__ bias, void* __restrict__ Cv,
    int M, int N, int K, const unsigned char* __restrict__ rowmask)
{
    __shared__ __align__(128) __nv_bfloat16 As[2][128 * 32];
    __shared__ __align__(128) __nv_bfloat16 Bs[2][128 * 32];

    const int tid  = threadIdx.x;
    const int lane = tid & 31;
    const int wid  = tid >> 5;
    const int wr   = wid & 1;
    const int wc   = wid >> 1;
    const int gid  = lane >> 2;
    const int tig  = lane & 3;
    const int brow = blockIdx.y * 128;
    const int bcol = blockIdx.x * 128;

    const int r_st = tid >> 3;
    const int kq   = (tid & 7) * 4;
    const int sts_col = (tid & 7) * 8;
    const int b_row_cp = tid >> 2;
    const int b_cg     = (tid & 3);

    float acc[4][4][4];
    #pragma unroll
    for (int i = 0; i < 4; i++)
        #pragma unroll
        for (int j = 0; j < 4; j++)
            #pragma unroll
            for (int l = 0; l < 4; l++) acc[i][j][l] = 0.f;

    const uint32_t asb = (uint32_t)__cvta_generic_to_shared(&As[0][0]);
    const uint32_t bsb = (uint32_t)__cvta_generic_to_shared(&Bs[0][0]);
    const uint32_t bufoff = 128 * 32 * 2;

    const int a_row = (lane & 7) + ((lane >> 3) & 1) * 8;
    const int a_col = (lane >> 4) * 16;
    const int b_row = (lane & 7) + ((lane >> 4) & 1) * 8;
    const int b_col = ((lane >> 3) & 1) * 16;

    uint2 pa[4];

    #define LD_A(kc) do {                                                               \
        _Pragma("unroll")                                                               \
        for (int i = 0; i < 4; i++) {                                                   \
            int gr = brow + r_st + 32 * i; if (gr >= M) gr = M - 1;                     \
            float4 v = *reinterpret_cast<const float4*>(A + (size_t)gr * K + (kc) + kq);\
            pa[i].x = packbf(v.x, v.y); pa[i].y = packbf(v.z, v.w);                     \
        }                                                                               \
    } while (0)

    #define ST_A(buf) do {                                                              \
        char* sa = reinterpret_cast<char*>(&As[buf][0]);                                \
        _Pragma("unroll")                                                               \
        for (int i = 0; i < 4; i++)                                                     \
            *reinterpret_cast<uint2*>(sa + SW64((r_st + 32 * i) * 64 + sts_col)) = pa[i];\
    } while (0)

    #define CPA_B(kc, buf) do {                                                         \
        _Pragma("unroll")                                                               \
        for (int j = 0; j < 2; j++) {                                                   \
            int row = b_row_cp + 64 * j;                                                \
            cpa16(bsb + (buf) * bufoff + SW64(row * 64 + b_cg * 16),                    \
                  Bb + (size_t)(bcol + row) * K + (kc) + b_cg * 8);                     \
        }                                                                               \
    } while (0)

    const int KT = K >> 5;
    CPA_B(0, 0);
    CPA_COMMIT();
    LD_A(0);
    ST_A(0);
    CPA_WAIT0();
    __syncthreads();

    for (int kt = 0; kt < KT; kt++) {
        const int buf = kt & 1;
        if (kt + 1 < KT) {
            CPA_B((kt + 1) * 32, buf ^ 1);
            CPA_COMMIT();
            LD_A((kt + 1) * 32);
        }

        const uint32_t ab = asb + buf * bufoff;
        const uint32_t bb = bsb + buf * bufoff;
        #pragma unroll
        for (int ks = 0; ks < 2; ks++) {
            uint32_t af[4][4], bfq[2][4];
            #pragma unroll
            for (int mt = 0; mt < 4; mt++)
                ldmx4(af[mt], ab + SW64((wr * 64 + mt * 16 + a_row) * 64 + a_col + ks * 32));
            #pragma unroll
            for (int p = 0; p < 2; p++)
                ldmx4(bfq[p], bb + SW64((wc * 32 + p * 16 + b_row) * 64 + b_col + ks * 32));
            #pragma unroll
            for (int mt = 0; mt < 4; mt++)
                #pragma unroll
                for (int nt = 0; nt < 4; nt++)
                    mma_bf16(acc[mt][nt], af[mt], &bfq[nt >> 1][(nt & 1) * 2]);
        }

        if (kt + 1 < KT) {
            ST_A(buf ^ 1);
            CPA_WAIT0();
            __syncthreads();
        }
    }
    #undef LD_A
    #undef ST_A
    #undef CPA_B

    float* Cf = (float*)Cv;
    __nv_bfloat16* Cb = (__nv_bfloat16*)Cv;

    #pragma unroll
    for (int mt = 0; mt < 4; mt++) {
        const int r0 = brow + wr * 64 + mt * 16 + gid;
        const int r1 = r0 + 8;
        const bool v0 = r0 < M, v1 = r1 < M;
        bool z0 = false, z1 = false;
        if (MASK) {
            if (v0) z0 = (rowmask[r0] != 0);
            if (v1) z1 = (rowmask[r1] != 0);
        }
        #pragma unroll
        for (int nt = 0; nt < 4; nt++) {
            const int col = bcol + wc * 32 + nt * 8 + 2 * tig;
            const float b0 = bias[col], b1 = bias[col + 1];
            float2 u, v;
            u.x = acc[mt][nt][0] + b0; u.y = acc[mt][nt][1] + b1;
            v.x = acc[mt][nt][2] + b0; v.y = acc[mt][nt][3] + b1;
            if (ACT == 1) {
                u.x = fmaxf(u.x, 0.f); u.y = fmaxf(u.y, 0.f);
                v.x = fmaxf(v.x, 0.f); v.y = fmaxf(v.y, 0.f);
            }
            if (MASK) {
                if (z0) { u.x = 0.f; u.y = 0.f; }
                if (z1) { v.x = 0.f; v.y = 0.f; }
            }
            if (OUT == 0) {
                if (v0) *reinterpret_cast<float2*>(Cf + (size_t)r0 * N + col) = u;
                if (v1) *reinterpret_cast<float2*>(Cf + (size_t)r1 * N + col) = v;
            } else {
                __nv_bfloat162 hu = __floats2bfloat162_rn(u.x, u.y);
                __nv_bfloat162 hv = __floats2bfloat162_rn(v.x, v.y);
                if (v0) *reinterpret_cast<__nv_bfloat162*>(Cb + (size_t)r0 * N + col) = hu;
                if (v1) *reinterpret_cast<__nv_bfloat162*>(Cb + (size_t)r1 * N + col) = hv;
            }
        }
    }
}

// ================= bf16x3 GEMM (oa): ~fp32 precision =================
__global__ void __launch_bounds__(256, 2) mma_gemm_x3(
    const float* __restrict__ A, const float* __restrict__ A2,
    const __nv_bfloat16* __restrict__ Bh, const __nv_bfloat16* __restrict__ Bl,
    const float* __restrict__ bias, float* __restrict__ C,
    int M, int N, int K)
{
    __shared__ __align__(128) __nv_bfloat16 Ahs[128 * 32];
    __shared__ __align__(128) __nv_bfloat16 Als[128 * 32];
    __shared__ __align__(128) __nv_bfloat16 Bhs[128 * 32];
    __shared__ __align__(128) __nv_bfloat16 Bls[128 * 32];

    const int tid  = threadIdx.x;
    const int lane = tid & 31;
    const int wid  = tid >> 5;
    const int wr   = wid & 1;
    const int wc   = wid >> 1;
    const int gid  = lane >> 2;
    const int tig  = lane & 3;
    const int brow = blockIdx.y * 128;
    const int bcol = blockIdx.x * 128;

    const int r_st = tid >> 3;
    const int kq   = (tid & 7) * 4;
    const int sts_col = (tid & 7) * 8;
    const int b_row_cp = tid >> 2;
    const int b_cg     = (tid & 3);

    float acc[4][4][4];
    #pragma unroll
    for (int i = 0; i < 4; i++)
        #pragma unroll
        for (int j = 0; j < 4; j++)
            #pragma unroll
            for (int l = 0; l < 4; l++) acc[i][j][l] = 0.f;

    const uint32_t ahb = (uint32_t)__cvta_generic_to_shared(&Ahs[0]);
    const uint32_t alb = (uint32_t)__cvta_generic_to_shared(&Als[0]);
    const uint32_t bhb = (uint32_t)__cvta_generic_to_shared(&Bhs[0]);
    const uint32_t blb = (uint32_t)__cvta_generic_to_shared(&Bls[0]);

    const int a_row = (lane & 7) + ((lane >> 3) & 1) * 8;
    const int a_col = (lane >> 4) * 16;
    const int b_row = (lane & 7) + ((lane >> 4) & 1) * 8;
    const int b_col = ((lane >> 3) & 1) * 16;

    uint2 pah[4], pal[4];

    #define LD_AX(kc) do {                                                              \
        _Pragma("unroll")                                                               \
        for (int i = 0; i < 4; i++) {                                                   \
            int gr = brow + r_st + 32 * i; if (gr >= M) gr = M - 1;                     \
            float4 v  = *reinterpret_cast<const float4*>(A  + (size_t)gr * K + (kc) + kq);\
            float4 v2 = *reinterpret_cast<const float4*>(A2 + (size_t)gr * K + (kc) + kq);\
            v.x += v2.x; v.y += v2.y; v.z += v2.z; v.w += v2.w;                         \
            __nv_bfloat162 h0 = __floats2bfloat162_rn(v.x, v.y);                        \
            __nv_bfloat162 h1 = __floats2bfloat162_rn(v.z, v.w);                        \
            float2 f0 = __bfloat1622float2(h0);                                         \
            float2 f1 = __bfloat1622float2(h1);                                         \
            pah[i].x = *reinterpret_cast<uint32_t*>(&h0);                               \
            pah[i].y = *reinterpret_cast<uint32_t*>(&h1);                               \
            pal[i].x = packbf(v.x - f0.x, v.y - f0.y);                                  \
            pal[i].y = packbf(v.z - f1.x, v.w - f1.y);                                  \
        }                                                                               \
    } while (0)

    #define ST_AX() do {                                                                \
        char* sh = reinterpret_cast<char*>(&Ahs[0]);                                    \
        char* sl = reinterpret_cast<char*>(&Als[0]);                                    \
        _Pragma("unroll")                                                               \
        for (int i = 0; i < 4; i++) {                                                   \
            uint32_t o = SW64((r_st + 32 * i) * 64 + sts_col);                          \
            *reinterpret_cast<uint2*>(sh + o) = pah[i];                                 \
            *reinterpret_cast<uint2*>(sl + o) = pal[i];                                 \
        }                                                                               \
    } while (0)

    #define CPA_BX(kc) do {                                                             \
        _Pragma("unroll")                                                               \
        for (int j = 0; j < 2; j++) {                                                   \
            int row = b_row_cp + 64 * j;                                                \
            uint32_t o = SW64(row * 64 + b_cg * 16);                                    \
            size_t gsrc = (size_t)(bcol + row) * K + (kc) + b_cg * 8;                   \
            cpa16(bhb + o, Bh + gsrc);                                                  \
            cpa16(blb + o, Bl + gsrc);                                                  \
        }                                                                               \
    } while (0)

    const int KT = K >> 5;
    LD_AX(0);
    for (int kt = 0; kt < KT; kt++) {
        if (kt) __syncthreads();
        ST_AX();
        CPA_BX(kt * 32);
        CPA_COMMIT();
        if (kt + 1 < KT) LD_AX((kt + 1) * 32);
        CPA_WAIT0();
        __syncthreads();

        #pragma unroll
        for (int ks = 0; ks < 2; ks++) {
            uint32_t afh[4][4], bfh[2][4];
            #pragma unroll
            for (int mt = 0; mt < 4; mt++)
                ldmx4(afh[mt], ahb + SW64((wr * 64 + mt * 16 + a_row) * 64 + a_col + ks * 32));
            #pragma unroll
            for (int p = 0; p < 2; p++)
                ldmx4(bfh[p], bhb + SW64((wc * 32 + p * 16 + b_row) * 64 + b_col + ks * 32));
            #pragma unroll
            for (int mt = 0; mt < 4; mt++)
                #pragma unroll
                for (int nt = 0; nt < 4; nt++)
                    mma_bf16(acc[mt][nt], afh[mt], &bfh[nt >> 1][(nt & 1) * 2]);

            {
                uint32_t bfl[2][4];
                #pragma unroll
                for (int p = 0; p < 2; p++)
                    ldmx4(bfl[p], blb + SW64((wc * 32 + p * 16 + b_row) * 64 + b_col + ks * 32));
                #pragma unroll
                for (int mt = 0; mt < 4; mt++)
                    #pragma unroll
                    for (int nt = 0; nt < 4; nt++)
                        mma_bf16(acc[mt][nt], afh[mt], &bfl[nt >> 1][(nt & 1) * 2]);
            }
            {
                uint32_t afl[4][4];
                #pragma unroll
                for (int mt = 0; mt < 4; mt++)
                    ldmx4(afl[mt], alb + SW64((wr * 64 + mt * 16 + a_row) * 64 + a_col + ks * 32));
                #pragma unroll
                for (int mt = 0; mt < 4; mt++)
                    #pragma unroll
                    for (int nt = 0; nt < 4; nt++)
                        mma_bf16(acc[mt][nt], afl[mt], &bfh[nt >> 1][(nt & 1) * 2]);
            }
        }
    }
    #undef LD_AX
    #undef ST_AX
    #undef CPA_BX

    #pragma unroll
    for (int mt = 0; mt < 4; mt++) {
        const int r0 = brow + wr * 64 + mt * 16 + gid;
        const int r1 = r0 + 8;
        const bool v0 = r0 < M, v1 = r1 < M;
        #pragma unroll
        for (int nt = 0; nt < 4; nt++) {
            const int col = bcol + wc * 32 + nt * 8 + 2 * tig;
            const float b0 = bias[col], b1 = bias[col + 1];
            float2 u, v;
            u.x = acc[mt][nt][0] + b0; u.y = acc[mt][nt][1] + b1;
            v.x = acc[mt][nt][2] + b0; v.y = acc[mt][nt][3] + b1;
            if (v0) *reinterpret_cast<float2*>(C + (size_t)r0 * N + col) = u;
            if (v1) *reinterpret_cast<float2*>(C + (size_t)r1 * N + col) = v;
        }
    }
}

// ---------------- unified weight prep ----------------
__global__ void wprep_kernel(const float* __restrict__ Wv,  __nv_bfloat16* __restrict__ WvT,
                             const float* __restrict__ Wo,  __nv_bfloat16* __restrict__ WoT,
                             const float* __restrict__ W1,  __nv_bfloat16* __restrict__ W1T,
                             const float* __restrict__ W2,  __nv_bfloat16* __restrict__ W2T,
                             const float* __restrict__ Woff, const float* __restrict__ boff,
                             const float* __restrict__ Watt, const float* __restrict__ batt,
                             __nv_bfloat16* __restrict__ WoaTh, __nv_bfloat16* __restrict__ WoaTl,
                             float* __restrict__ boa)
{
    __shared__ float t[32][33];
    const int x = threadIdx.x, y = threadIdx.y;
    const int z = blockIdx.z;

    if (z == 4) {
        const int bx = blockIdx.x * 32;
        const int by = blockIdx.y * 32;
        if (bx >= NOA || by >= DIM) return;
        const bool isAtt = (bx >= 256);
        const float* W = isAtt ? Watt : Woff;
        const int    nN = isAtt ? 128 : 256;
        const int    nb = isAtt ? bx - 256 : bx;
        #pragma unroll
        for (int i = 0; i < 32; i += 8)
            t[y + i][x] = W[(size_t)(by + y + i) * nN + nb + x];
        __syncthreads();
        #pragma unroll
        for (int i = 0; i < 32; i += 8) {
            float w = t[x][y + i];
            __nv_bfloat16 h = __float2bfloat16(w);
            size_t idx = (size_t)(bx + y + i) * DIM + by + x;
            WoaTh[idx] = h;
            WoaTl[idx] = __float2bfloat16(w - __bfloat162float(h));
        }
        if (blockIdx.y == 0 && y == 0) {
            int n = bx + x;
            boa[n] = (n < 256) ? boff[n] : batt[n - 256];
        }
        return;
    }

    const float* W; __nv_bfloat16* Wt; int K, N;
    switch (z) {
        case 0: W = Wv; Wt = WvT; K = DIM; N = DIM; break;
        case 1: W = Wo; Wt = WoT; K = DIM; N = DIM; break;
        case 2: W = W1; Wt = W1T; K = DIM; N = DFF; break;
        default:W = W2; Wt = W2T; K = DFF; N = DIM; break;
    }
    const int bx = blockIdx.x * 32;
    const int by = blockIdx.y * 32;
    if (bx >= N || by >= K) return;
    #pragma unroll
    for (int i = 0; i < 32; i += 8)
        t[y + i][x] = W[(size_t)(by + y + i) * N + bx + x];
    __syncthreads();
    #pragma unroll
    for (int i = 0; i < 32; i += 8)
        Wt[(size_t)(bx + y + i) * K + by + x] = __float2bfloat16(t[x][y + i]);
}

// ---------------- MS-deform sampling v5: 4 queries/block, warp = 4 heads ----------
__device__ __forceinline__ void msda_corners(
    int l, float2 off, float refx, float refy, float wi,
    uint32_t* q, float* u)
{
    const int Hl = c_H[l], Wl = c_W[l], st = c_S[l];
    const float x = refx * (float)Wl + off.x - 0.5f;
    const float y = refy * (float)Hl + off.y - 0.5f;
    const float x0f = floorf(x), y0f = floorf(y);
    const float fx = x - x0f, fy = y - y0f;
    const int x0 = (int)x0f, y0 = (int)y0f;
    const int x1 = x0 + 1,   y1 = y0 + 1;
    const float vx0 = (x0 >= 0 && x0 < Wl) ? 1.f : 0.f;
    const float vx1 = (x1 >= 0 && x1 < Wl) ? 1.f : 0.f;
    const float vy0 = (y0 >= 0 && y0 < Hl) ? 1.f : 0.f;
    const float vy1 = (y1 >= 0 && y1 < Hl) ? 1.f : 0.f;
    const int xc0 = min(max(x0, 0), Wl - 1), xc1 = min(max(x1, 0), Wl - 1);
    const int yc0 = min(max(y0, 0), Hl - 1), yc1 = min(max(y1, 0), Hl - 1);
    q[0] = (uint32_t)(st + yc0 * Wl + xc0) * 512u;
    q[1] = (uint32_t)(st + yc0 * Wl + xc1) * 512u;
    q[2] = (uint32_t)(st + yc1 * Wl + xc0) * 512u;
    q[3] = (uint32_t)(st + yc1 * Wl + xc1) * 512u;
    u[0] = (1.f - fx) * (1.f - fy) * vx0 * vy0 * wi;
    u[1] = fx * (1.f - fy) * vx1 * vy0 * wi;
    u[2] = (1.f - fx) * fy * vx0 * vy1 * wi;
    u[3] = fx * fy * vx1 * vy1 * wi;
}

__global__ void __launch_bounds__(256) msda_kernel(
    const __nv_bfloat16* __restrict__ value,
    const float* __restrict__ oa,
    const float* __restrict__ refpts,
    float* __restrict__ samp)
{
    const int nq   = blockIdx.x * 4 + (threadIdx.x >> 6);   // 4 queries per block
    const int t64  = threadIdx.x & 63;
    const int w    = t64 >> 5;               // warp-in-query: heads 4w..4w+3
    const int lane = threadIdx.x & 31;
    const int g    = lane >> 3;
    const int ci   = lane & 7;
    const int h    = w * 4 + g;
    const int n    = nq / LQ;

    const float lg0 = oa[(size_t)nq * NOA + 256 + h * 16 + ci];
    const float lg1 = oa[(size_t)nq * NOA + 256 + h * 16 + ci + 8];
    float m = fmaxf(lg0, lg1);
    #pragma unroll
    for (int o = 4; o > 0; o >>= 1) m = fmaxf(m, __shfl_xor_sync(0xffffffffu, m, o, 8));
    const float e0 = __expf(lg0 - m), e1 = __expf(lg1 - m);
    float s = e0 + e1;
    #pragma unroll
    for (int o = 4; o > 0; o >>= 1) s += __shfl_xor_sync(0xffffffffu, s, o, 8);
    const float wi0 = e0 / s, wi1 = e1 / s;

    const float2 off0 = *reinterpret_cast<const float2*>(oa + (size_t)nq * NOA + h * 32 + 2 * ci);
    const float2 off1 = *reinterpret_cast<const float2*>(oa + (size_t)nq * NOA + h * 32 + 2 * (ci + 8));
    float2 refv = make_float2(0.f, 0.f);
    if (lane < 4) refv = *reinterpret_cast<const float2*>(refpts + (size_t)nq * 8 + 2 * lane);
    const int l0 = ci >> 2;
    const int l1 = l0 + 2;
    const float rx0 = __shfl_sync(0xffffffffu, refv.x, l0);
    const float ry0 = __shfl_sync(0xffffffffu, refv.y, l0);
    const float rx1 = __shfl_sync(0xffffffffu, refv.x, l1);
    const float ry1 = __shfl_sync(0xffffffffu, refv.y, l1);

    uint32_t q0[4], q1[4];
    float    u0[4], u1[4];
    msda_corners(l0, off0, rx0, ry0, wi0, q0, u0);
    msda_corners(l1, off1, rx1, ry1, wi1, q1, u1);

    const char* vb = reinterpret_cast<const char*>(
        value + ((size_t)n * LIN * HEADS + h) * HD + 4 * ci);

    float4 acc = make_float4(0.f, 0.f, 0.f, 0.f);

    #define GATHER(QARR, UARR, I) do {                                                  \
        const int src = g * 8 + (I);                                                    \
        const uint32_t qa = __shfl_sync(0xffffffffu, (QARR)[0], src);                   \
        const uint32_t qb = __shfl_sync(0xffffffffu, (QARR)[1], src);                   \
        const uint32_t qc = __shfl_sync(0xffffffffu, (QARR)[2], src);                   \
        const uint32_t qd = __shfl_sync(0xffffffffu, (QARR)[3], src);                   \
        const float ua = __shfl_sync(0xffffffffu, (UARR)[0], src);                      \
        const float ub = __shfl_sync(0xffffffffu, (UARR)[1], src);                      \
        const float uc = __shfl_sync(0xffffffffu, (UARR)[2], src);                      \
        const float ud = __shfl_sync(0xffffffffu, (UARR)[3], src);                      \
        const uint2 va = *reinterpret_cast<const uint2*>(vb + qa);                      \
        const uint2 vvb = *reinterpret_cast<const uint2*>(vb + qb);                     \
        const uint2 vc = *reinterpret_cast<const uint2*>(vb + qc);                      \
        const uint2 vd = *reinterpret_cast<const uint2*>(vb + qd);                      \
        float2 alo = __bfloat1622float2(*reinterpret_cast<const __nv_bfloat162*>(&va.x)); \
        float2 ahi = __bfloat1622float2(*reinterpret_cast<const __nv_bfloat162*>(&va.y)); \
        float2 blo = __bfloat1622float2(*reinterpret_cast<const __nv_bfloat162*>(&vvb.x)); \
        float2 bhi = __bfloat1622float2(*reinterpret_cast<const __nv_bfloat162*>(&vvb.y)); \
        float2 clo = __bfloat1622float2(*reinterpret_cast<const __nv_bfloat162*>(&vc.x)); \
        float2 chi = __bfloat1622float2(*reinterpret_cast<const __nv_bfloat162*>(&vc.y)); \
        float2 dlo = __bfloat1622float2(*reinterpret_cast<const __nv_bfloat162*>(&vd.x)); \
        float2 dhi = __bfloat1622float2(*reinterpret_cast<const __nv_bfloat162*>(&vd.y)); \
        acc.x += ua * alo.x + ub * blo.x + uc * clo.x + ud * dlo.x;                     \
        acc.y += ua * alo.y + ub * blo.y + uc * clo.y + ud * dlo.y;                     \
        acc.z += ua * ahi.x + ub * bhi.x + uc * chi.x + ud * dhi.x;                     \
        acc.w += ua * ahi.y + ub * bhi.y + uc * chi.y + ud * dhi.y;                     \
    } while (0)

    #pragma unroll
    for (int i = 0; i < 8; i++) GATHER(q0, u0, i);
    #pragma unroll
    for (int i = 0; i < 8; i++) GATHER(q1, u1, i);
    #undef GATHER

    *reinterpret_cast<float4*>(samp + (size_t)nq * 256 + h * 32 + 4 * ci) = acc;
}

// ---------------- fused residual + LayerNorm (warp per row) ----------------
__global__ void ln_kernel(const float* __restrict__ a, const float* __restrict__ b,
                          const float* __restrict__ g, const float* __restrict__ be,
                          float* __restrict__ out)
{
    const int row  = blockIdx.x * 8 + (threadIdx.x >> 5);
    const int lane = threadIdx.x & 31;
    const size_t base = (size_t)row * 256;

    float4 a0 = *reinterpret_cast<const float4*>(a + base + lane * 4);
    float4 a1 = *reinterpret_cast<const float4*>(a + base + 128 + lane * 4);
    float4 b0 = *reinterpret_cast<const float4*>(b + base + lane * 4);
    float4 b1 = *reinterpret_cast<const float4*>(b + base + 128 + lane * 4);
    float x0 = a0.x + b0.x, x1 = a0.y + b0.y, x2 = a0.z + b0.z, x3 = a0.w + b0.w;
    float x4 = a1.x + b1.x, x5 = a1.y + b1.y, x6 = a1.z + b1.z, x7 = a1.w + b1.w;

    float s  = x0 + x1 + x2 + x3 + x4 + x5 + x6 + x7;
    float s2 = x0*x0 + x1*x1 + x2*x2 + x3*x3 + x4*x4 + x5*x5 + x6*x6 + x7*x7;
    #pragma unroll
    for (int o = 16; o > 0; o >>= 1) {
        s  += __shfl_xor_sync(0xffffffffu, s,  o);
        s2 += __shfl_xor_sync(0xffffffffu, s2, o);
    }
    const float mean = s * (1.f / 256.f);
    const float rstd = rsqrtf(s2 * (1.f / 256.f) - mean * mean + 1e-5f);

    float4 g0 = *reinterpret_cast<const float4*>(g + lane * 4);
    float4 g1 = *reinterpret_cast<const float4*>(g + 128 + lane * 4);
    float4 e0 = *reinterpret_cast<const float4*>(be + lane * 4);
    float4 e1 = *reinterpret_cast<const float4*>(be + 128 + lane * 4);

    float4 o0, o1;
    o0.x = (x0 - mean) * rstd * g0.x + e0.x;
    o0.y = (x1 - mean) * rstd * g0.y + e0.y;
    o0.z = (x2 - mean) * rstd * g0.z + e0.z;
    o0.w = (x3 - mean) * rstd * g0.w + e0.w;
    o1.x = (x4 - mean) * rstd * g1.x + e1.x;
    o1.y = (x5 - mean) * rstd * g1.y + e1.y;
    o1.z = (x6 - mean) * rstd * g1.z + e1.z;
    o1.w = (x7 - mean) * rstd * g1.w + e1.w;
    *reinterpret_cast<float4*>(out + base + lane * 4)       = o0;
    *reinterpret_cast<float4*>(out + base + 128 + lane * 4) = o1;
}

// ---------------- launch ----------------
extern "C" void kernel_launch(void* const* d_in, const int* in_sizes, int n_in,
                              void* d_out, int out_size)
{
    const float* pre_tgt  = (const float*)d_in[0];
    const float* pre_qpos = (const float*)d_in[1];
    const float* src      = (const float*)d_in[2];
    const float* ref_pts  = (const float*)d_in[3];
    const unsigned char* mask = (const unsigned char*)d_in[4];
    const float* W_value = (const float*)d_in[7];
    const float* b_value = (const float*)d_in[8];
    const float* W_off   = (const float*)d_in[9];
    const float* b_off   = (const float*)d_in[10];
    const float* W_attn  = (const float*)d_in[11];
    const float* b_attn  = (const float*)d_in[12];
    const float* W_out   = (const float*)d_in[13];
    const float* b_out   = (const float*)d_in[14];
    const float* g1      = (const float*)d_in[15];
    const float* be1     = (const float*)d_in[16];
    const float* W1      = (const float*)d_in[17];
    const float* b1      = (const float*)d_in[18];
    const float* W2      = (const float*)d_in[19];
    const float* b2      = (const float*)d_in[20];
    const float* g3      = (const float*)d_in[21];
    const float* be3     = (const float*)d_in[22];

    __nv_bfloat16 *p_value, *p_WvTb, *p_WoutTb, *p_W1Tb, *p_W2Tb, *p_WoaTh, *p_WoaTl;
    float *p_oa, *p_samp, *p_ms, *p_tgt, *p_ffh, *p_ff, *p_boa;
    cudaGetSymbolAddress((void**)&p_value, g_value);
    cudaGetSymbolAddress((void**)&p_oa,    g_oa);
    cudaGetSymbolAddress((void**)&p_samp,  g_samp);
    cudaGetSymbolAddress((void**)&p_ms,    g_ms);
    cudaGetSymbolAddress((void**)&p_tgt,   g_tgt);
    cudaGetSymbolAddress((void**)&p_ffh,   g_ffh);
    cudaGetSymbolAddress((void**)&p_ff,    g_ff);
    cudaGetSymbolAddress((void**)&p_WvTb,  g_WvTb);
    cudaGetSymbolAddress((void**)&p_WoutTb,g_WoutTb);
    cudaGetSymbolAddress((void**)&p_W1Tb,  g_W1Tb);
    cudaGetSymbolAddress((void**)&p_W2Tb,  g_W2Tb);
    cudaGetSymbolAddress((void**)&p_WoaTh, g_WoaTh);
    cudaGetSymbolAddress((void**)&p_WoaTl, g_WoaTl);
    cudaGetSymbolAddress((void**)&p_boa,   g_boa);

    const int MV = NB * LIN;   // 174080
    dim3 tb(32, 8);

    // 1. unified weight prep
    wprep_kernel<<<dim3(16, 16, 5), tb>>>(W_value, p_WvTb, W_out, p_WoutTb,
                                          W1, p_W1Tb, W2, p_W2Tb,
                                          W_off, b_off, W_attn, b_attn,
                                          p_WoaTh, p_WoaTl, p_boa);
    // 2. value = mask(src @ Wv + bv) -> bf16
    mma_gemm_v6<0, true, 1><<<dim3(2, MV / 128), 256>>>(
        src, p_WvTb, b_value, p_value, MV, DIM, DIM, mask);
    // 3. oa = (pre_tgt + pre_qpos) @ [Woff|Wattn] + bias   (bf16x3)
    mma_gemm_x3<<<dim3(NOA / 128, (NQ + 127) / 128), 256>>>(
        pre_tgt, pre_qpos, p_WoaTh, p_WoaTl, p_boa, p_oa, NQ, NOA, DIM);
    // 4. sampling v5: 4 queries/block (launch #4 -> profiled)
    msda_kernel<<<NQ / 4, 256>>>(p_value, p_oa, ref_pts, p_samp);
    // 5. ms = samp @ Wout + bout
    mma_gemm_v6<0, false, 0><<<dim3(2, (NQ + 127) / 128), 256>>>(
        p_samp, p_WoutTb, b_out, p_ms, NQ, DIM, DIM, nullptr);
    // 6. tgt = LN(pre_tgt + ms)
    ln_kernel<<<NQ / 8, 256>>>(pre_tgt, p_ms, g1, be1, p_tgt);
    // 7. ffh = relu(tgt @ W1 + b1)
    mma_gemm_v6<1, false, 0><<<dim3(4, (NQ + 127) / 128), 256>>>(
        p_tgt, p_W1Tb, b1, p_ffh, NQ, DFF, DIM, nullptr);
    // 8. ff = ffh @ W2 + b2
    mma_gemm_v6<0, false, 0><<<dim3(2, (NQ + 127) / 128), 256>>>(
        p_ffh, p_W2Tb, b2, p_ff, NQ, DIM, DFF, nullptr);
    // 9. out = LN(tgt + ff)
    ln_kernel<<<NQ / 8, 256>>>(p_tgt, p_ff, g3, be3, (float*)d_out);
}

// round 16
// speedup vs baseline: 1.0908x; 1.0041x over previous
#include <cuda_runtime.h>
#include <cuda_bf16.h>
#include <cstdint>

// ---------------- Problem constants ----------------
#define NB   8
#define LQ   1000
#define NQ   (NB*LQ)
#define DIM  256
#define HEADS 8
#define HD   32
#define LIN  21760
#define DFF  512
#define NOA  384

__device__ __constant__ int c_H[4]  = {128, 64, 32, 16};
__device__ __constant__ int c_W[4]  = {128, 64, 32, 16};
__device__ __constant__ int c_S[4]  = {0, 16384, 20480, 21504};

// ---------------- Scratch ----------------
__device__ __nv_bfloat16 g_value[(size_t)LIN * NB * DIM];
__device__ float g_oa   [(size_t)NQ * NOA];
__device__ float g_samp [(size_t)NQ * DIM];
__device__ float g_tgt  [(size_t)NQ * DIM];
__device__ float g_ffh  [(size_t)NQ * DFF];
__device__ __nv_bfloat16 g_WvTb [DIM * DIM];
__device__ __nv_bfloat16 g_WoutTb[DIM * DIM];
__device__ __nv_bfloat16 g_W1Tb [DFF * DIM];
__device__ __nv_bfloat16 g_W2Tb [DIM * DFF];
__device__ __nv_bfloat16 g_WoaTh[NOA * DIM];
__device__ __nv_bfloat16 g_WoaTl[NOA * DIM];
__device__ float g_boa  [NOA];

// ---------------- helpers ----------------
__device__ __forceinline__ void mma_bf16(float* d, const uint32_t* a, const uint32_t* b) {
    asm volatile(
        "mma.sync.aligned.m16n8k16.row.col.f32.bf16.bf16.f32 "
        "{%0,%1,%2,%3}, {%4,%5,%6,%7}, {%8,%9}, {%0,%1,%2,%3};"
        : "+f"(d[0]), "+f"(d[1]), "+f"(d[2]), "+f"(d[3])
        : "r"(a[0]), "r"(a[1]), "r"(a[2]), "r"(a[3]), "r"(b[0]), "r"(b[1]));
}
__device__ __forceinline__ void ldmx4(uint32_t* r, uint32_t addr) {
    asm volatile("ldmatrix.sync.aligned.m8n8.x4.shared.b16 {%0,%1,%2,%3}, [%4];"
        : "=r"(r[0]), "=r"(r[1]), "=r"(r[2]), "=r"(r[3]) : "r"(addr));
}
__device__ __forceinline__ uint32_t packbf(float lo, float hi) {
    __nv_bfloat162 h = __floats2bfloat162_rn(lo, hi);
    return *reinterpret_cast<uint32_t*>(&h);
}
__device__ __forceinline__ void cpa16(uint32_t dst, const void* src) {
    asm volatile("cp.async.cg.shared.global [%0], [%1], 16;" :: "r"(dst), "l"(src) : "memory");
}
#define CPA_COMMIT() asm volatile("cp.async.commit_group;" ::: "memory")
#define CPA_WAIT0()  asm volatile("cp.async.wait_group 0;"  ::: "memory")
#define SW64(o) ((uint32_t)(o) ^ (((uint32_t)(o) >> 3) & 0x30u))

// ================= bf16 mma GEMM v6 (BM=128 — best measured config) =========
template<int ACT, bool MASK, int OUT>
__global__ void __launch_bounds__(256, 2) mma_gemm_v6(
    const float* __restrict__ A, const __nv_bfloat16* __restrict__ Bb,
    const float* __restrict__ bias, void* __restrict__ Cv,
    int M, int N, int K, const unsigned char* __restrict__ rowmask)
{
    __shared__ __align__(128) __nv_bfloat16 As[2][128 * 32];
    __shared__ __align__(128) __nv_bfloat16 Bs[2][128 * 32];

    const int tid  = threadIdx.x;
    const int lane = tid & 31;
    const int wid  = tid >> 5;
    const int wr   = wid & 1;
    const int wc   = wid >> 1;
    const int gid  = lane >> 2;
    const int tig  = lane & 3;
    const int brow = blockIdx.y * 128;
    const int bcol = blockIdx.x * 128;

    const int r_st = tid >> 3;
    const int kq   = (tid & 7) * 4;
    const int sts_col = (tid & 7) * 8;
    const int b_row_cp = tid >> 2;
    const int b_cg     = (tid & 3);

    float acc[4][4][4];
    #pragma unroll
    for (int i = 0; i < 4; i++)
        #pragma unroll
        for (int j = 0; j < 4; j++)
            #pragma unroll
            for (int l = 0; l < 4; l++) acc[i][j][l] = 0.f;

    const uint32_t asb = (uint32_t)__cvta_generic_to_shared(&As[0][0]);
    const uint32_t bsb = (uint32_t)__cvta_generic_to_shared(&Bs[0][0]);
    const uint32_t bufoff = 128 * 32 * 2;

    const int a_row = (lane & 7) + ((lane >> 3) & 1) * 8;
    const int a_col = (lane >> 4) * 16;
    const int b_row = (lane & 7) + ((lane >> 4) & 1) * 8;
    const int b_col = ((lane >> 3) & 1) * 16;

    uint2 pa[4];

    #define LD_A(kc) do {                                                               \
        _Pragma("unroll")                                                               \
        for (int i = 0; i < 4; i++) {                                                   \
            int gr = brow + r_st + 32 * i; if (gr >= M) gr = M - 1;                     \
            float4 v = *reinterpret_cast<const float4*>(A + (size_t)gr * K + (kc) + kq);\
            pa[i].x = packbf(v.x, v.y); pa[i].y = packbf(v.z, v.w);                     \
        }                                                                               \
    } while (0)

    #define ST_A(buf) do {                                                              \
        char* sa = reinterpret_cast<char*>(&As[buf][0]);                                \
        _Pragma("unroll")                                                               \
        for (int i = 0; i < 4; i++)                                                     \
            *reinterpret_cast<uint2*>(sa + SW64((r_st + 32 * i) * 64 + sts_col)) = pa[i];\
    } while (0)

    #define CPA_B(kc, buf) do {                                                         \
        _Pragma("unroll")                                                               \
        for (int j = 0; j < 2; j++) {                                                   \
            int row = b_row_cp + 64 * j;                                                \
            cpa16(bsb + (buf) * bufoff + SW64(row * 64 + b_cg * 16),                    \
                  Bb + (size_t)(bcol + row) * K + (kc) + b_cg * 8);                     \
        }                                                                               \
    } while (0)

    const int KT = K >> 5;
    CPA_B(0, 0);
    CPA_COMMIT();
    LD_A(0);
    ST_A(0);
    CPA_WAIT0();
    __syncthreads();

    for (int kt = 0; kt < KT; kt++) {
        const int buf = kt & 1;
        if (kt + 1 < KT) {
            CPA_B((kt + 1) * 32, buf ^ 1);
            CPA_COMMIT();
            LD_A((kt + 1) * 32);
        }

        const uint32_t ab = asb + buf * bufoff;
        const uint32_t bb = bsb + buf * bufoff;
        #pragma unroll
        for (int ks = 0; ks < 2; ks++) {
            uint32_t af[4][4], bfq[2][4];
            #pragma unroll
            for (int mt = 0; mt < 4; mt++)
                ldmx4(af[mt], ab + SW64((wr * 64 + mt * 16 + a_row) * 64 + a_col + ks * 32));
            #pragma unroll
            for (int p = 0; p < 2; p++)
                ldmx4(bfq[p], bb + SW64((wc * 32 + p * 16 + b_row) * 64 + b_col + ks * 32));
            #pragma unroll
            for (int mt = 0; mt < 4; mt++)
                #pragma unroll
                for (int nt = 0; nt < 4; nt++)
                    mma_bf16(acc[mt][nt], af[mt], &bfq[nt >> 1][(nt & 1) * 2]);
        }

        if (kt + 1 < KT) {
            ST_A(buf ^ 1);
            CPA_WAIT0();
            __syncthreads();
        }
    }
    #undef LD_A
    #undef ST_A
    #undef CPA_B

    float* Cf = (float*)Cv;
    __nv_bfloat16* Cb = (__nv_bfloat16*)Cv;

    #pragma unroll
    for (int mt = 0; mt < 4; mt++) {
        const int r0 = brow + wr * 64 + mt * 16 + gid;
        const int r1 = r0 + 8;
        const bool v0 = r0 < M, v1 = r1 < M;
        bool z0 = false, z1 = false;
        if (MASK) {
            if (v0) z0 = (rowmask[r0] != 0);
            if (v1) z1 = (rowmask[r1] != 0);
        }
        #pragma unroll
        for (int nt = 0; nt < 4; nt++) {
            const int col = bcol + wc * 32 + nt * 8 + 2 * tig;
            const float b0 = bias[col], b1 = bias[col + 1];
            float2 u, v;
            u.x = acc[mt][nt][0] + b0; u.y = acc[mt][nt][1] + b1;
            v.x = acc[mt][nt][2] + b0; v.y = acc[mt][nt][3] + b1;
            if (ACT == 1) {
                u.x = fmaxf(u.x, 0.f); u.y = fmaxf(u.y, 0.f);
                v.x = fmaxf(v.x, 0.f); v.y = fmaxf(v.y, 0.f);
            }
            if (MASK) {
                if (z0) { u.x = 0.f; u.y = 0.f; }
                if (z1) { v.x = 0.f; v.y = 0.f; }
            }
            if (OUT == 0) {
                if (v0) *reinterpret_cast<float2*>(Cf + (size_t)r0 * N + col) = u;
                if (v1) *reinterpret_cast<float2*>(Cf + (size_t)r1 * N + col) = v;
            } else {
                __nv_bfloat162 hu = __floats2bfloat162_rn(u.x, u.y);
                __nv_bfloat162 hv = __floats2bfloat162_rn(v.x, v.y);
                if (v0) *reinterpret_cast<__nv_bfloat162*>(Cb + (size_t)r0 * N + col) = hu;
                if (v1) *reinterpret_cast<__nv_bfloat162*>(Cb + (size_t)r1 * N + col) = hv;
            }
        }
    }
}

// ================= fused GEMM + residual + LayerNorm =================
// Out = LN(resid + A @ Bb^T + bias). BM=64, BN=256 (full row), BK=32.
// 8 warps 2x4, warp tile 32x64. grid = M/64 (M mult of 64). K mult of 32.
__global__ void __launch_bounds__(256, 2) mma_gemm_ln(
    const float* __restrict__ A, const __nv_bfloat16* __restrict__ Bb,
    const float* __restrict__ bias, const float* __restrict__ resid,
    const float* __restrict__ g, const float* __restrict__ be,
    float* __restrict__ Out, int M, int K)
{
    __shared__ __align__(128) __nv_bfloat16 As[2][64 * 32];    // 8 KB
    __shared__ __align__(128) __nv_bfloat16 Bs[2][256 * 32];   // 32 KB
    __shared__ float s_sum[64][4];
    __shared__ float s_sq [64][4];
    __shared__ float s_mean[64], s_rstd[64];

    const int tid  = threadIdx.x;
    const int lane = tid & 31;
    const int wid  = tid >> 5;
    const int wr   = wid & 1;       // 2 warp rows of 32
    const int wc   = wid >> 1;      // 4 warp cols of 64
    const int gid  = lane >> 2;
    const int tig  = lane & 3;
    const int brow = blockIdx.x * 64;

    const int r_st = tid >> 3;
    const int kq   = (tid & 7) * 4;
    const int sts_col = (tid & 7) * 8;

    float acc[2][8][4];
    #pragma unroll
    for (int i = 0; i < 2; i++)
        #pragma unroll
        for (int j = 0; j < 8; j++)
            #pragma unroll
            for (int l = 0; l < 4; l++) acc[i][j][l] = 0.f;

    const uint32_t asb = (uint32_t)__cvta_generic_to_shared(&As[0][0]);
    const uint32_t bsb = (uint32_t)__cvta_generic_to_shared(&Bs[0][0]);
    const uint32_t abufoff = 64 * 32 * 2;
    const uint32_t bbufoff = 256 * 32 * 2;

    const int a_row = (lane & 7) + ((lane >> 3) & 1) * 8;
    const int a_col = (lane >> 4) * 16;
    const int b_row = (lane & 7) + ((lane >> 4) & 1) * 8;
    const int b_col = ((lane >> 3) & 1) * 16;

    uint2 pa[2];

    #define LD_A(kc) do {                                                               \
        _Pragma("unroll")                                                               \
        for (int i = 0; i < 2; i++) {                                                   \
            int gr = brow + r_st + 32 * i;                                              \
            float4 v = *reinterpret_cast<const float4*>(A + (size_t)gr * K + (kc) + kq);\
            pa[i].x = packbf(v.x, v.y); pa[i].y = packbf(v.z, v.w);                     \
        }                                                                               \
    } while (0)

    #define ST_A(buf) do {                                                              \
        char* sa = reinterpret_cast<char*>(&As[buf][0]);                                \
        _Pragma("unroll")                                                               \
        for (int i = 0; i < 2; i++)                                                     \
            *reinterpret_cast<uint2*>(sa + SW64((r_st + 32 * i) * 64 + sts_col)) = pa[i];\
    } while (0)

    // B: 256 rows x 32 bf16 = 1024 x 16B chunks; 4 per thread
    #define CPA_B(kc, buf) do {                                                         \
        _Pragma("unroll")                                                               \
        for (int j = 0; j < 4; j++) {                                                   \
            int c = tid + 256 * j;                                                      \
            int row = c >> 2, cg = c & 3;                                               \
            cpa16(bsb + (buf) * bbufoff + SW64(row * 64 + cg * 16),                     \
                  Bb + (size_t)row * K + (kc) + cg * 8);                                \
        }                                                                               \
    } while (0)

    const int KT = K >> 5;
    CPA_B(0, 0);
    CPA_COMMIT();
    LD_A(0);
    ST_A(0);
    CPA_WAIT0();
    __syncthreads();

    for (int kt = 0; kt < KT; kt++) {
        const int buf = kt & 1;
        if (kt + 1 < KT) {
            CPA_B((kt + 1) * 32, buf ^ 1);
            CPA_COMMIT();
            LD_A((kt + 1) * 32);
        }

        const uint32_t ab = asb + buf * abufoff;
        const uint32_t bb = bsb + buf * bbufoff;
        #pragma unroll
        for (int ks = 0; ks < 2; ks++) {
            uint32_t af[2][4], bfq[4][4];
            #pragma unroll
            for (int mt = 0; mt < 2; mt++)
                ldmx4(af[mt], ab + SW64((wr * 32 + mt * 16 + a_row) * 64 + a_col + ks * 32));
            #pragma unroll
            for (int p = 0; p < 4; p++)
                ldmx4(bfq[p], bb + SW64((wc * 64 + p * 16 + b_row) * 64 + b_col + ks * 32));
            #pragma unroll
            for (int mt = 0; mt < 2; mt++)
                #pragma unroll
                for (int nt = 0; nt < 8; nt++)
                    mma_bf16(acc[mt][nt], af[mt], &bfq[nt >> 1][(nt & 1) * 2]);
        }

        if (kt + 1 < KT) {
            ST_A(buf ^ 1);
            CPA_WAIT0();
            __syncthreads();
        }
    }
    #undef LD_A
    #undef ST_A
    #undef CPA_B

    // ---- epilogue: val = acc + bias + resid; row stats; LN ----
    float sp[2][2] = {{0.f,0.f},{0.f,0.f}};   // [mt][rr] row sums
    float qp[2][2] = {{0.f,0.f},{0.f,0.f}};   // sumsq
    #pragma unroll
    for (int mt = 0; mt < 2; mt++) {
        const int r0 = brow + wr * 32 + mt * 16 + gid;
        const int r1 = r0 + 8;
        #pragma unroll
        for (int nt = 0; nt < 8; nt++) {
            const int col = wc * 64 + nt * 8 + 2 * tig;
            const float b0 = bias[col], b1 = bias[col + 1];
            float2 e0 = *reinterpret_cast<const float2*>(resid + (size_t)r0 * 256 + col);
            float2 e1 = *reinterpret_cast<const float2*>(resid + (size_t)r1 * 256 + col);
            acc[mt][nt][0] += b0 + e0.x;  acc[mt][nt][1] += b1 + e0.y;
            acc[mt][nt][2] += b0 + e1.x;  acc[mt][nt][3] += b1 + e1.y;
            sp[mt][0] += acc[mt][nt][0] + acc[mt][nt][1];
            sp[mt][1] += acc[mt][nt][2] + acc[mt][nt][3];
            qp[mt][0] += acc[mt][nt][0]*acc[mt][nt][0] + acc[mt][nt][1]*acc[mt][nt][1];
            qp[mt][1] += acc[mt][nt][2]*acc[mt][nt][2] + acc[mt][nt][3]*acc[mt][nt][3];
        }
    }
    // reduce over tig (lanes gid*4 .. gid*4+3)
    #pragma unroll
    for (int o = 1; o <= 2; o <<= 1) {
        #pragma unroll
        for (int mt = 0; mt < 2; mt++)
            #pragma unroll
            for (int rr = 0; rr < 2; rr++) {
                sp[mt][rr] += __shfl_xor_sync(0xffffffffu, sp[mt][rr], o);
                qp[mt][rr] += __shfl_xor_sync(0xffffffffu, qp[mt][rr], o);
            }
    }
    if (tig == 0) {
        #pragma unroll
        for (int mt = 0; mt < 2; mt++)
            #pragma unroll
            for (int rr = 0; rr < 2; rr++) {
                const int rl = wr * 32 + mt * 16 + rr * 8 + gid;
                s_sum[rl][wc] = sp[mt][rr];
                s_sq [rl][wc] = qp[mt][rr];
            }
    }
    __syncthreads();
    if (tid < 64) {
        float S  = s_sum[tid][0] + s_sum[tid][1] + s_sum[tid][2] + s_sum[tid][3];
        float S2 = s_sq [tid][0] + s_sq [tid][1] + s_sq [tid][2] + s_sq [tid][3];
        const float mean = S * (1.f / 256.f);
        s_mean[tid] = mean;
        s_rstd[tid] = rsqrtf(S2 * (1.f / 256.f) - mean * mean + 1e-5f);
    }
    __syncthreads();

    #pragma unroll
    for (int mt = 0; mt < 2; mt++) {
        const int rl0 = wr * 32 + mt * 16 + gid;
        const int rl1 = rl0 + 8;
        const float m0 = s_mean[rl0], rs0 = s_rstd[rl0];
        const float m1 = s_mean[rl1], rs1 = s_rstd[rl1];
        const int r0 = brow + rl0, r1 = brow + rl1;
        #pragma unroll
        for (int nt = 0; nt < 8; nt++) {
            const int col = wc * 64 + nt * 8 + 2 * tig;
            float2 gg = *reinterpret_cast<const float2*>(g  + col);
            float2 ee = *reinterpret_cast<const float2*>(be + col);
            float2 u, v;
            u.x = (acc[mt][nt][0] - m0) * rs0 * gg.x + ee.x;
            u.y = (acc[mt][nt][1] - m0) * rs0 * gg.y + ee.y;
            v.x = (acc[mt][nt][2] - m1) * rs1 * gg.x + ee.x;
            v.y = (acc[mt][nt][3] - m1) * rs1 * gg.y + ee.y;
            *reinterpret_cast<float2*>(Out + (size_t)r0 * 256 + col) = u;
            *reinterpret_cast<float2*>(Out + (size_t)r1 * 256 + col) = v;
        }
    }
}

// ================= bf16x3 GEMM (oa): ~fp32 precision =================
__global__ void __launch_bounds__(256, 2) mma_gemm_x3(
    const float* __restrict__ A, const float* __restrict__ A2,
    const __nv_bfloat16* __restrict__ Bh, const __nv_bfloat16* __restrict__ Bl,
    const float* __restrict__ bias, float* __restrict__ C,
    int M, int N, int K)
{
    __shared__ __align__(128) __nv_bfloat16 Ahs[128 * 32];
    __shared__ __align__(128) __nv_bfloat16 Als[128 * 32];
    __shared__ __align__(128) __nv_bfloat16 Bhs[128 * 32];
    __shared__ __align__(128) __nv_bfloat16 Bls[128 * 32];

    const int tid  = threadIdx.x;
    const int lane = tid & 31;
    const int wid  = tid >> 5;
    const int wr   = wid & 1;
    const int wc   = wid >> 1;
    const int gid  = lane >> 2;
    const int tig  = lane & 3;
    const int brow = blockIdx.y * 128;
    const int bcol = blockIdx.x * 128;

    const int r_st = tid >> 3;
    const int kq   = (tid & 7) * 4;
    const int sts_col = (tid & 7) * 8;
    const int b_row_cp = tid >> 2;
    const int b_cg     = (tid & 3);

    float acc[4][4][4];
    #pragma unroll
    for (int i = 0; i < 4; i++)
        #pragma unroll
        for (int j = 0; j < 4; j++)
            #pragma unroll
            for (int l = 0; l < 4; l++) acc[i][j][l] = 0.f;

    const uint32_t ahb = (uint32_t)__cvta_generic_to_shared(&Ahs[0]);
    const uint32_t alb = (uint32_t)__cvta_generic_to_shared(&Als[0]);
    const uint32_t bhb = (uint32_t)__cvta_generic_to_shared(&Bhs[0]);
    const uint32_t blb = (uint32_t)__cvta_generic_to_shared(&Bls[0]);

    const int a_row = (lane & 7) + ((lane >> 3) & 1) * 8;
    const int a_col = (lane >> 4) * 16;
    const int b_row = (lane & 7) + ((lane >> 4) & 1) * 8;
    const int b_col = ((lane >> 3) & 1) * 16;

    uint2 pah[4], pal[4];

    #define LD_AX(kc) do {                                                              \
        _Pragma("unroll")                                                               \
        for (int i = 0; i < 4; i++) {                                                   \
            int gr = brow + r_st + 32 * i; if (gr >= M) gr = M - 1;                     \
            float4 v  = *reinterpret_cast<const float4*>(A  + (size_t)gr * K + (kc) + kq);\
            float4 v2 = *reinterpret_cast<const float4*>(A2 + (size_t)gr * K + (kc) + kq);\
            v.x += v2.x; v.y += v2.y; v.z += v2.z; v.w += v2.w;                         \
            __nv_bfloat162 h0 = __floats2bfloat162_rn(v.x, v.y);                        \
            __nv_bfloat162 h1 = __floats2bfloat162_rn(v.z, v.w);                        \
            float2 f0 = __bfloat1622float2(h0);                                         \
            float2 f1 = __bfloat1622float2(h1);                                         \
            pah[i].x = *reinterpret_cast<uint32_t*>(&h0);                               \
            pah[i].y = *reinterpret_cast<uint32_t*>(&h1);                               \
            pal[i].x = packbf(v.x - f0.x, v.y - f0.y);                                  \
            pal[i].y = packbf(v.z - f1.x, v.w - f1.y);                                  \
        }                                                                               \
    } while (0)

    #define ST_AX() do {                                                                \
        char* sh = reinterpret_cast<char*>(&Ahs[0]);                                    \
        char* sl = reinterpret_cast<char*>(&Als[0]);                                    \
        _Pragma("unroll")                                                               \
        for (int i = 0; i < 4; i++) {                                                   \
            uint32_t o = SW64((r_st + 32 * i) * 64 + sts_col);                          \
            *reinterpret_cast<uint2*>(sh + o) = pah[i];                                 \
            *reinterpret_cast<uint2*>(sl + o) = pal[i];                                 \
        }                                                                               \
    } while (0)

    #define CPA_BX(kc) do {                                                             \
        _Pragma("unroll")                                                               \
        for (int j = 0; j < 2; j++) {                                                   \
            int row = b_row_cp + 64 * j;                                                \
            uint32_t o = SW64(row * 64 + b_cg * 16);                                    \
            size_t gsrc = (size_t)(bcol + row) * K + (kc) + b_cg * 8;                   \
            cpa16(bhb + o, Bh + gsrc);                                                  \
            cpa16(blb + o, Bl + gsrc);                                                  \
        }                                                                               \
    } while (0)

    const int KT = K >> 5;
    LD_AX(0);
    for (int kt = 0; kt < KT; kt++) {
        if (kt) __syncthreads();
        ST_AX();
        CPA_BX(kt * 32);
        CPA_COMMIT();
        if (kt + 1 < KT) LD_AX((kt + 1) * 32);
        CPA_WAIT0();
        __syncthreads();

        #pragma unroll
        for (int ks = 0; ks < 2; ks++) {
            uint32_t afh[4][4], bfh[2][4];
            #pragma unroll
            for (int mt = 0; mt < 4; mt++)
                ldmx4(afh[mt], ahb + SW64((wr * 64 + mt * 16 + a_row) * 64 + a_col + ks * 32));
            #pragma unroll
            for (int p = 0; p < 2; p++)
                ldmx4(bfh[p], bhb + SW64((wc * 32 + p * 16 + b_row) * 64 + b_col + ks * 32));
            #pragma unroll
            for (int mt = 0; mt < 4; mt++)
                #pragma unroll
                for (int nt = 0; nt < 4; nt++)
                    mma_bf16(acc[mt][nt], afh[mt], &bfh[nt >> 1][(nt & 1) * 2]);

            {
                uint32_t bfl[2][4];
                #pragma unroll
                for (int p = 0; p < 2; p++)
                    ldmx4(bfl[p], blb + SW64((wc * 32 + p * 16 + b_row) * 64 + b_col + ks * 32));
                #pragma unroll
                for (int mt = 0; mt < 4; mt++)
                    #pragma unroll
                    for (int nt = 0; nt < 4; nt++)
                        mma_bf16(acc[mt][nt], afh[mt], &bfl[nt >> 1][(nt & 1) * 2]);
            }
            {
                uint32_t afl[4][4];
                #pragma unroll
                for (int mt = 0; mt < 4; mt++)
                    ldmx4(afl[mt], alb + SW64((wr * 64 + mt * 16 + a_row) * 64 + a_col + ks * 32));
                #pragma unroll
                for (int mt = 0; mt < 4; mt++)
                    #pragma unroll
                    for (int nt = 0; nt < 4; nt++)
                        mma_bf16(acc[mt][nt], afl[mt], &bfh[nt >> 1][(nt & 1) * 2]);
            }
        }
    }
    #undef LD_AX
    #undef ST_AX
    #undef CPA_BX

    #pragma unroll
    for (int mt = 0; mt < 4; mt++) {
        const int r0 = brow + wr * 64 + mt * 16 + gid;
        const int r1 = r0 + 8;
        const bool v0 = r0 < M, v1 = r1 < M;
        #pragma unroll
        for (int nt = 0; nt < 4; nt++) {
            const int col = bcol + wc * 32 + nt * 8 + 2 * tig;
            const float b0 = bias[col], b1 = bias[col + 1];
            float2 u, v;
            u.x = acc[mt][nt][0] + b0; u.y = acc[mt][nt][1] + b1;
            v.x = acc[mt][nt][2] + b0; v.y = acc[mt][nt][3] + b1;
            if (v0) *reinterpret_cast<float2*>(C + (size_t)r0 * N + col) = u;
            if (v1) *reinterpret_cast<float2*>(C + (size_t)r1 * N + col) = v;
        }
    }
}

// ---------------- unified weight prep ----------------
__global__ void wprep_kernel(const float* __restrict__ Wv,  __nv_bfloat16* __restrict__ WvT,
                             const float* __restrict__ Wo,  __nv_bfloat16* __restrict__ WoT,
                             const float* __restrict__ W1,  __nv_bfloat16* __restrict__ W1T,
                             const float* __restrict__ W2,  __nv_bfloat16* __restrict__ W2T,
                             const float* __restrict__ Woff, const float* __restrict__ boff,
                             const float* __restrict__ Watt, const float* __restrict__ batt,
                             __nv_bfloat16* __restrict__ WoaTh, __nv_bfloat16* __restrict__ WoaTl,
                             float* __restrict__ boa)
{
    __shared__ float t[32][33];
    const int x = threadIdx.x, y = threadIdx.y;
    const int z = blockIdx.z;

    if (z == 4) {
        const int bx = blockIdx.x * 32;
        const int by = blockIdx.y * 32;
        if (bx >= NOA || by >= DIM) return;
        const bool isAtt = (bx >= 256);
        const float* W = isAtt ? Watt : Woff;
        const int    nN = isAtt ? 128 : 256;
        const int    nb = isAtt ? bx - 256 : bx;
        #pragma unroll
        for (int i = 0; i < 32; i += 8)
            t[y + i][x] = W[(size_t)(by + y + i) * nN + nb + x];
        __syncthreads();
        #pragma unroll
        for (int i = 0; i < 32; i += 8) {
            float w = t[x][y + i];
            __nv_bfloat16 h = __float2bfloat16(w);
            size_t idx = (size_t)(bx + y + i) * DIM + by + x;
            WoaTh[idx] = h;
            WoaTl[idx] = __float2bfloat16(w - __bfloat162float(h));
        }
        if (blockIdx.y == 0 && y == 0) {
            int n = bx + x;
            boa[n] = (n < 256) ? boff[n] : batt[n - 256];
        }
        return;
    }

    const float* W; __nv_bfloat16* Wt; int K, N;
    switch (z) {
        case 0: W = Wv; Wt = WvT; K = DIM; N = DIM; break;
        case 1: W = Wo; Wt = WoT; K = DIM; N = DIM; break;
        case 2: W = W1; Wt = W1T; K = DIM; N = DFF; break;
        default:W = W2; Wt = W2T; K = DFF; N = DIM; break;
    }
    const int bx = blockIdx.x * 32;
    const int by = blockIdx.y * 32;
    if (bx >= N || by >= K) return;
    #pragma unroll
    for (int i = 0; i < 32; i += 8)
        t[y + i][x] = W[(size_t)(by + y + i) * N + bx + x];
    __syncthreads();
    #pragma unroll
    for (int i = 0; i < 32; i += 8)
        Wt[(size_t)(bx + y + i) * K + by + x] = __float2bfloat16(t[x][y + i]);
}

// ---------------- MS-deform sampling v5 (plateaued — frozen) ----------
__device__ __forceinline__ void msda_corners(
    int l, float2 off, float refx, float refy, float wi,
    uint32_t* q, float* u)
{
    const int Hl = c_H[l], Wl = c_W[l], st = c_S[l];
    const float x = refx * (float)Wl + off.x - 0.5f;
    const float y = refy * (float)Hl + off.y - 0.5f;
    const float x0f = floorf(x), y0f = floorf(y);
    const float fx = x - x0f, fy = y - y0f;
    const int x0 = (int)x0f, y0 = (int)y0f;
    const int x1 = x0 + 1,   y1 = y0 + 1;
    const float vx0 = (x0 >= 0 && x0 < Wl) ? 1.f : 0.f;
    const float vx1 = (x1 >= 0 && x1 < Wl) ? 1.f : 0.f;
    const float vy0 = (y0 >= 0 && y0 < Hl) ? 1.f : 0.f;
    const float vy1 = (y1 >= 0 && y1 < Hl) ? 1.f : 0.f;
    const int xc0 = min(max(x0, 0), Wl - 1), xc1 = min(max(x1, 0), Wl - 1);
    const int yc0 = min(max(y0, 0), Hl - 1), yc1 = min(max(y1, 0), Hl - 1);
    q[0] = (uint32_t)(st + yc0 * Wl + xc0) * 512u;
    q[1] = (uint32_t)(st + yc0 * Wl + xc1) * 512u;
    q[2] = (uint32_t)(st + yc1 * Wl + xc0) * 512u;
    q[3] = (uint32_t)(st + yc1 * Wl + xc1) * 512u;
    u[0] = (1.f - fx) * (1.f - fy) * vx0 * vy0 * wi;
    u[1] = fx * (1.f - fy) * vx1 * vy0 * wi;
    u[2] = (1.f - fx) * fy * vx0 * vy1 * wi;
    u[3] = fx * fy * vx1 * vy1 * wi;
}

__global__ void __launch_bounds__(256) msda_kernel(
    const __nv_bfloat16* __restrict__ value,
    const float* __restrict__ oa,
    const float* __restrict__ refpts,
    float* __restrict__ samp)
{
    const int nq   = blockIdx.x * 4 + (threadIdx.x >> 6);
    const int t64  = threadIdx.x & 63;
    const int w    = t64 >> 5;
    const int lane = threadIdx.x & 31;
    const int g    = lane >> 3;
    const int ci   = lane & 7;
    const int h    = w * 4 + g;
    const int n    = nq / LQ;

    const float lg0 = oa[(size_t)nq * NOA + 256 + h * 16 + ci];
    const float lg1 = oa[(size_t)nq * NOA + 256 + h * 16 + ci + 8];
    float m = fmaxf(lg0, lg1);
    #pragma unroll
    for (int o = 4; o > 0; o >>= 1) m = fmaxf(m, __shfl_xor_sync(0xffffffffu, m, o, 8));
    const float e0 = __expf(lg0 - m), e1 = __expf(lg1 - m);
    float s = e0 + e1;
    #pragma unroll
    for (int o = 4; o > 0; o >>= 1) s += __shfl_xor_sync(0xffffffffu, s, o, 8);
    const float wi0 = e0 / s, wi1 = e1 / s;

    const float2 off0 = *reinterpret_cast<const float2*>(oa + (size_t)nq * NOA + h * 32 + 2 * ci);
    const float2 off1 = *reinterpret_cast<const float2*>(oa + (size_t)nq * NOA + h * 32 + 2 * (ci + 8));
    float2 refv = make_float2(0.f, 0.f);
    if (lane < 4) refv = *reinterpret_cast<const float2*>(refpts + (size_t)nq * 8 + 2 * lane);
    const int l0 = ci >> 2;
    const int l1 = l0 + 2;
    const float rx0 = __shfl_sync(0xffffffffu, refv.x, l0);
    const float ry0 = __shfl_sync(0xffffffffu, refv.y, l0);
    const float rx1 = __shfl_sync(0xffffffffu, refv.x, l1);
    const float ry1 = __shfl_sync(0xffffffffu, refv.y, l1);

    uint32_t q0[4], q1[4];
    float    u0[4], u1[4];
    msda_corners(l0, off0, rx0, ry0, wi0, q0, u0);
    msda_corners(l1, off1, rx1, ry1, wi1, q1, u1);

    const char* vb = reinterpret_cast<const char*>(
        value + ((size_t)n * LIN * HEADS + h) * HD + 4 * ci);

    float4 acc = make_float4(0.f, 0.f, 0.f, 0.f);

    #define GATHER(QARR, UARR, I) do {                                                  \
        const int src = g * 8 + (I);                                                    \
        const uint32_t qa = __shfl_sync(0xffffffffu, (QARR)[0], src);                   \
        const uint32_t qb = __shfl_sync(0xffffffffu, (QARR)[1], src);                   \
        const uint32_t qc = __shfl_sync(0xffffffffu, (QARR)[2], src);                   \
        const uint32_t qd = __shfl_sync(0xffffffffu, (QARR)[3], src);                   \
        const float ua = __shfl_sync(0xffffffffu, (UARR)[0], src);                      \
        const float ub = __shfl_sync(0xffffffffu, (UARR)[1], src);                      \
        const float uc = __shfl_sync(0xffffffffu, (UARR)[2], src);                      \
        const float ud = __shfl_sync(0xffffffffu, (UARR)[3], src);                      \
        const uint2 va = *reinterpret_cast<const uint2*>(vb + qa);                      \
        const uint2 vvb = *reinterpret_cast<const uint2*>(vb + qb);                     \
        const uint2 vc = *reinterpret_cast<const uint2*>(vb + qc);                      \
        const uint2 vd = *reinterpret_cast<const uint2*>(vb + qd);                      \
        float2 alo = __bfloat1622float2(*reinterpret_cast<const __nv_bfloat162*>(&va.x)); \
        float2 ahi = __bfloat1622float2(*reinterpret_cast<const __nv_bfloat162*>(&va.y)); \
        float2 blo = __bfloat1622float2(*reinterpret_cast<const __nv_bfloat162*>(&vvb.x)); \
        float2 bhi = __bfloat1622float2(*reinterpret_cast<const __nv_bfloat162*>(&vvb.y)); \
        float2 clo = __bfloat1622float2(*reinterpret_cast<const __nv_bfloat162*>(&vc.x)); \
        float2 chi = __bfloat1622float2(*reinterpret_cast<const __nv_bfloat162*>(&vc.y)); \
        float2 dlo = __bfloat1622float2(*reinterpret_cast<const __nv_bfloat162*>(&vd.x)); \
        float2 dhi = __bfloat1622float2(*reinterpret_cast<const __nv_bfloat162*>(&vd.y)); \
        acc.x += ua * alo.x + ub * blo.x + uc * clo.x + ud * dlo.x;                     \
        acc.y += ua * alo.y + ub * blo.y + uc * clo.y + ud * dlo.y;                     \
        acc.z += ua * ahi.x + ub * bhi.x + uc * chi.x + ud * dhi.x;                     \
        acc.w += ua * ahi.y + ub * bhi.y + uc * chi.y + ud * dhi.y;                     \
    } while (0)

    #pragma unroll
    for (int i = 0; i < 8; i++) GATHER(q0, u0, i);
    #pragma unroll
    for (int i = 0; i < 8; i++) GATHER(q1, u1, i);
    #undef GATHER

    *reinterpret_cast<float4*>(samp + (size_t)nq * 256 + h * 32 + 4 * ci) = acc;
}

// ---------------- launch ----------------
extern "C" void kernel_launch(void* const* d_in, const int* in_sizes, int n_in,
                              void* d_out, int out_size)
{
    const float* pre_tgt  = (const float*)d_in[0];
    const float* pre_qpos = (const float*)d_in[1];
    const float* src      = (const float*)d_in[2];
    const float* ref_pts  = (const float*)d_in[3];
    const unsigned char* mask = (const unsigned char*)d_in[4];
    const float* W_value = (const float*)d_in[7];
    const float* b_value = (const float*)d_in[8];
    const float* W_off   = (const float*)d_in[9];
    const float* b_off   = (const float*)d_in[10];
    const float* W_attn  = (const float*)d_in[11];
    const float* b_attn  = (const float*)d_in[12];
    const float* W_out   = (const float*)d_in[13];
    const float* b_out   = (const float*)d_in[14];
    const float* g1      = (const float*)d_in[15];
    const float* be1     = (const float*)d_in[16];
    const float* W1      = (const float*)d_in[17];
    const float* b1      = (const float*)d_in[18];
    const float* W2      = (const float*)d_in[19];
    const float* b2      = (const float*)d_in[20];
    const float* g3      = (const float*)d_in[21];
    const float* be3     = (const float*)d_in[22];

    __nv_bfloat16 *p_value, *p_WvTb, *p_WoutTb, *p_W1Tb, *p_W2Tb, *p_WoaTh, *p_WoaTl;
    float *p_oa, *p_samp, *p_tgt, *p_ffh, *p_boa;
    cudaGetSymbolAddress((void**)&p_value, g_value);
    cudaGetSymbolAddress((void**)&p_oa,    g_oa);
    cudaGetSymbolAddress((void**)&p_samp,  g_samp);
    cudaGetSymbolAddress((void**)&p_tgt,   g_tgt);
    cudaGetSymbolAddress((void**)&p_ffh,   g_ffh);
    cudaGetSymbolAddress((void**)&p_WvTb,  g_WvTb);
    cudaGetSymbolAddress((void**)&p_WoutTb,g_WoutTb);
    cudaGetSymbolAddress((void**)&p_W1Tb,  g_W1Tb);
    cudaGetSymbolAddress((void**)&p_W2Tb,  g_W2Tb);
    cudaGetSymbolAddress((void**)&p_WoaTh, g_WoaTh);
    cudaGetSymbolAddress((void**)&p_WoaTl, g_WoaTl);
    cudaGetSymbolAddress((void**)&p_boa,   g_boa);

    const int MV = NB * LIN;   // 174080
    dim3 tb(32, 8);

    // 1. unified weight prep
    wprep_kernel<<<dim3(16, 16, 5), tb>>>(W_value, p_WvTb, W_out, p_WoutTb,
                                          W1, p_W1Tb, W2, p_W2Tb,
                                          W_off, b_off, W_attn, b_attn,
                                          p_WoaTh, p_WoaTl, p_boa);
    // 2. value = mask(src @ Wv + bv) -> bf16
    mma_gemm_v6<0, true, 1><<<dim3(2, MV / 128), 256>>>(
        src, p_WvTb, b_value, p_value, MV, DIM, DIM, mask);
    // 3. oa = (pre_tgt + pre_qpos) @ [Woff|Wattn] + bias   (bf16x3)
    mma_gemm_x3<<<dim3(NOA / 128, (NQ + 127) / 128), 256>>>(
        pre_tgt, pre_qpos, p_WoaTh, p_WoaTl, p_boa, p_oa, NQ, NOA, DIM);
    // 4. sampling v5 (launch #4 -> profiled)
    msda_kernel<<<NQ / 4, 256>>>(p_value, p_oa, ref_pts, p_samp);
    // 5. tgt = LN(pre_tgt + samp @ Wout + bout)   [fused]
    mma_gemm_ln<<<NQ / 64, 256>>>(
        p_samp, p_WoutTb, b_out, pre_tgt, g1, be1, p_tgt, NQ, DIM);
    // 6. ffh = relu(tgt @ W1 + b1)
    mma_gemm_v6<1, false, 0><<<dim3(4, (NQ + 127) / 128), 256>>>(
        p_tgt, p_W1Tb, b1, p_ffh, NQ, DFF, DIM, nullptr);
    // 7. out = LN(tgt + ffh @ W2 + b2)   [fused]
    mma_gemm_ln<<<NQ / 64, 256>>>(
        p_ffh, p_W2Tb, b2, p_tgt, g3, be3, (float*)d_out, NQ, DFF);
}

// round 17
// speedup vs baseline: 1.1219x; 1.0285x over previous
#include <cuda_runtime.h>
#include <cuda_bf16.h>
#include <cstdint>

// ---------------- Problem constants ----------------
#define NB   8
#define LQ   1000
#define NQ   (NB*LQ)
#define DIM  256
#define HEADS 8
#define HD   32
#define LIN  21760
#define DFF  512
#define NOA  384

__device__ __constant__ int c_H[4]  = {128, 64, 32, 16};
__device__ __constant__ int c_W[4]  = {128, 64, 32, 16};
__device__ __constant__ int c_S[4]  = {0, 16384, 20480, 21504};

// ---------------- Scratch ----------------
__device__ __nv_bfloat16 g_value[(size_t)LIN * NB * DIM];
__device__ float g_oa   [(size_t)NQ * NOA];
__device__ float g_samp [(size_t)NQ * DIM];
__device__ float g_tgt  [(size_t)NQ * DIM];
__device__ float g_ffh  [(size_t)NQ * DFF];
__device__ __nv_bfloat16 g_WvTb [DIM * DIM];
__device__ __nv_bfloat16 g_WoutTb[DIM * DIM];
__device__ __nv_bfloat16 g_W1Tb [DFF * DIM];
__device__ __nv_bfloat16 g_W2Tb [DIM * DFF];
__device__ __nv_bfloat16 g_WoaTh[NOA * DIM];
__device__ __nv_bfloat16 g_WoaTl[NOA * DIM];
__device__ float g_boa  [NOA];

// ---------------- helpers ----------------
__device__ __forceinline__ void mma_bf16(float* d, const uint32_t* a, const uint32_t* b) {
    asm volatile(
        "mma.sync.aligned.m16n8k16.row.col.f32.bf16.bf16.f32 "
        "{%0,%1,%2,%3}, {%4,%5,%6,%7}, {%8,%9}, {%0,%1,%2,%3};"
        : "+f"(d[0]), "+f"(d[1]), "+f"(d[2]), "+f"(d[3])
        : "r"(a[0]), "r"(a[1]), "r"(a[2]), "r"(a[3]), "r"(b[0]), "r"(b[1]));
}
__device__ __forceinline__ void ldmx4(uint32_t* r, uint32_t addr) {
    asm volatile("ldmatrix.sync.aligned.m8n8.x4.shared.b16 {%0,%1,%2,%3}, [%4];"
        : "=r"(r[0]), "=r"(r[1]), "=r"(r[2]), "=r"(r[3]) : "r"(addr));
}
__device__ __forceinline__ uint32_t packbf(float lo, float hi) {
    __nv_bfloat162 h = __floats2bfloat162_rn(lo, hi);
    return *reinterpret_cast<uint32_t*>(&h);
}
__device__ __forceinline__ void cpa16(uint32_t dst, const void* src) {
    asm volatile("cp.async.cg.shared.global [%0], [%1], 16;" :: "r"(dst), "l"(src) : "memory");
}
#define CPA_COMMIT() asm volatile("cp.async.commit_group;" ::: "memory")
#define CPA_WAIT0()  asm volatile("cp.async.wait_group 0;"  ::: "memory")
#define SW64(o) ((uint32_t)(o) ^ (((uint32_t)(o) >> 3) & 0x30u))

// ================= bf16 mma GEMM v6 (BM=128 — best measured config) =========
template<int ACT, bool MASK, int OUT>
__global__ void __launch_bounds__(256, 2) mma_gemm_v6(
    const float* __restrict__ A, const __nv_bfloat16* __restrict__ Bb,
    const float* __restrict__ bias, void* __restrict__ Cv,
    int M, int N, int K, const unsigned char* __restrict__ rowmask)
{
    __shared__ __align__(128) __nv_bfloat16 As[2][128 * 32];
    __shared__ __align__(128) __nv_bfloat16 Bs[2][128 * 32];

    const int tid  = threadIdx.x;
    const int lane = tid & 31;
    const int wid  = tid >> 5;
    const int wr   = wid & 1;
    const int wc   = wid >> 1;
    const int gid  = lane >> 2;
    const int tig  = lane & 3;
    const int brow = blockIdx.y * 128;
    const int bcol = blockIdx.x * 128;

    const int r_st = tid >> 3;
    const int kq   = (tid & 7) * 4;
    const int sts_col = (tid & 7) * 8;
    const int b_row_cp = tid >> 2;
    const int b_cg     = (tid & 3);

    float acc[4][4][4];
    #pragma unroll
    for (int i = 0; i < 4; i++)
        #pragma unroll
        for (int j = 0; j < 4; j++)
            #pragma unroll
            for (int l = 0; l < 4; l++) acc[i][j][l] = 0.f;

    const uint32_t asb = (uint32_t)__cvta_generic_to_shared(&As[0][0]);
    const uint32_t bsb = (uint32_t)__cvta_generic_to_shared(&Bs[0][0]);
    const uint32_t bufoff = 128 * 32 * 2;

    const int a_row = (lane & 7) + ((lane >> 3) & 1) * 8;
    const int a_col = (lane >> 4) * 16;
    const int b_row = (lane & 7) + ((lane >> 4) & 1) * 8;
    const int b_col = ((lane >> 3) & 1) * 16;

    uint2 pa[4];

    #define LD_A(kc) do {                                                               \
        _Pragma("unroll")                                                               \
        for (int i = 0; i < 4; i++) {                                                   \
            int gr = brow + r_st + 32 * i; if (gr >= M) gr = M - 1;                     \
            float4 v = *reinterpret_cast<const float4*>(A + (size_t)gr * K + (kc) + kq);\
            pa[i].x = packbf(v.x, v.y); pa[i].y = packbf(v.z, v.w);                     \
        }                                                                               \
    } while (0)

    #define ST_A(buf) do {                                                              \
        char* sa = reinterpret_cast<char*>(&As[buf][0]);                                \
        _Pragma("unroll")                                                               \
        for (int i = 0; i < 4; i++)                                                     \
            *reinterpret_cast<uint2*>(sa + SW64((r_st + 32 * i) * 64 + sts_col)) = pa[i];\
    } while (0)

    #define CPA_B(kc, buf) do {                                                         \
        _Pragma("unroll")                                                               \
        for (int j = 0; j < 2; j++) {                                                   \
            int row = b_row_cp + 64 * j;                                                \
            cpa16(bsb + (buf) * bufoff + SW64(row * 64 + b_cg * 16),                    \
                  Bb + (size_t)(bcol + row) * K + (kc) + b_cg * 8);                     \
        }                                                                               \
    } while (0)

    const int KT = K >> 5;
    CPA_B(0, 0);
    CPA_COMMIT();
    LD_A(0);
    ST_A(0);
    CPA_WAIT0();
    __syncthreads();

    for (int kt = 0; kt < KT; kt++) {
        const int buf = kt & 1;
        if (kt + 1 < KT) {
            CPA_B((kt + 1) * 32, buf ^ 1);
            CPA_COMMIT();
            LD_A((kt + 1) * 32);
        }

        const uint32_t ab = asb + buf * bufoff;
        const uint32_t bb = bsb + buf * bufoff;
        #pragma unroll
        for (int ks = 0; ks < 2; ks++) {
            uint32_t af[4][4], bfq[2][4];
            #pragma unroll
            for (int mt = 0; mt < 4; mt++)
                ldmx4(af[mt], ab + SW64((wr * 64 + mt * 16 + a_row) * 64 + a_col + ks * 32));
            #pragma unroll
            for (int p = 0; p < 2; p++)
                ldmx4(bfq[p], bb + SW64((wc * 32 + p * 16 + b_row) * 64 + b_col + ks * 32));
            #pragma unroll
            for (int mt = 0; mt < 4; mt++)
                #pragma unroll
                for (int nt = 0; nt < 4; nt++)
                    mma_bf16(acc[mt][nt], af[mt], &bfq[nt >> 1][(nt & 1) * 2]);
        }

        if (kt + 1 < KT) {
            ST_A(buf ^ 1);
            CPA_WAIT0();
            __syncthreads();
        }
    }
    #undef LD_A
    #undef ST_A
    #undef CPA_B

    float* Cf = (float*)Cv;
    __nv_bfloat16* Cb = (__nv_bfloat16*)Cv;

    #pragma unroll
    for (int mt = 0; mt < 4; mt++) {
        const int r0 = brow + wr * 64 + mt * 16 + gid;
        const int r1 = r0 + 8;
        const bool v0 = r0 < M, v1 = r1 < M;
        bool z0 = false, z1 = false;
        if (MASK) {
            if (v0) z0 = (rowmask[r0] != 0);
            if (v1) z1 = (rowmask[r1] != 0);
        }
        #pragma unroll
        for (int nt = 0; nt < 4; nt++) {
            const int col = bcol + wc * 32 + nt * 8 + 2 * tig;
            const float b0 = bias[col], b1 = bias[col + 1];
            float2 u, v;
            u.x = acc[mt][nt][0] + b0; u.y = acc[mt][nt][1] + b1;
            v.x = acc[mt][nt][2] + b0; v.y = acc[mt][nt][3] + b1;
            if (ACT == 1) {
                u.x = fmaxf(u.x, 0.f); u.y = fmaxf(u.y, 0.f);
                v.x = fmaxf(v.x, 0.f); v.y = fmaxf(v.y, 0.f);
            }
            if (MASK) {
                if (z0) { u.x = 0.f; u.y = 0.f; }
                if (z1) { v.x = 0.f; v.y = 0.f; }
            }
            if (OUT == 0) {
                if (v0) *reinterpret_cast<float2*>(Cf + (size_t)r0 * N + col) = u;
                if (v1) *reinterpret_cast<float2*>(Cf + (size_t)r1 * N + col) = v;
            } else {
                __nv_bfloat162 hu = __floats2bfloat162_rn(u.x, u.y);
                __nv_bfloat162 hv = __floats2bfloat162_rn(v.x, v.y);
                if (v0) *reinterpret_cast<__nv_bfloat162*>(Cb + (size_t)r0 * N + col) = hu;
                if (v1) *reinterpret_cast<__nv_bfloat162*>(Cb + (size_t)r1 * N + col) = hv;
            }
        }
    }
}

// ================= fused GEMM + residual + LayerNorm =================
__global__ void __launch_bounds__(256, 2) mma_gemm_ln(
    const float* __restrict__ A, const __nv_bfloat16* __restrict__ Bb,
    const float* __restrict__ bias, const float* __restrict__ resid,
    const float* __restrict__ g, const float* __restrict__ be,
    float* __restrict__ Out, int M, int K)
{
    __shared__ __align__(128) __nv_bfloat16 As[2][64 * 32];
    __shared__ __align__(128) __nv_bfloat16 Bs[2][256 * 32];
    __shared__ float s_sum[64][4];
    __shared__ float s_sq [64][4];
    __shared__ float s_mean[64], s_rstd[64];

    const int tid  = threadIdx.x;
    const int lane = tid & 31;
    const int wid  = tid >> 5;
    const int wr   = wid & 1;
    const int wc   = wid >> 1;
    const int gid  = lane >> 2;
    const int tig  = lane & 3;
    const int brow = blockIdx.x * 64;

    const int r_st = tid >> 3;
    const int kq   = (tid & 7) * 4;
    const int sts_col = (tid & 7) * 8;

    float acc[2][8][4];
    #pragma unroll
    for (int i = 0; i < 2; i++)
        #pragma unroll
        for (int j = 0; j < 8; j++)
            #pragma unroll
            for (int l = 0; l < 4; l++) acc[i][j][l] = 0.f;

    const uint32_t asb = (uint32_t)__cvta_generic_to_shared(&As[0][0]);
    const uint32_t bsb = (uint32_t)__cvta_generic_to_shared(&Bs[0][0]);
    const uint32_t abufoff = 64 * 32 * 2;
    const uint32_t bbufoff = 256 * 32 * 2;

    const int a_row = (lane & 7) + ((lane >> 3) & 1) * 8;
    const int a_col = (lane >> 4) * 16;
    const int b_row = (lane & 7) + ((lane >> 4) & 1) * 8;
    const int b_col = ((lane >> 3) & 1) * 16;

    uint2 pa[2];

    #define LD_A(kc) do {                                                               \
        _Pragma("unroll")                                                               \
        for (int i = 0; i < 2; i++) {                                                   \
            int gr = brow + r_st + 32 * i;                                              \
            float4 v = *reinterpret_cast<const float4*>(A + (size_t)gr * K + (kc) + kq);\
            pa[i].x = packbf(v.x, v.y); pa[i].y = packbf(v.z, v.w);                     \
        }                                                                               \
    } while (0)

    #define ST_A(buf) do {                                                              \
        char* sa = reinterpret_cast<char*>(&As[buf][0]);                                \
        _Pragma("unroll")                                                               \
        for (int i = 0; i < 2; i++)                                                     \
            *reinterpret_cast<uint2*>(sa + SW64((r_st + 32 * i) * 64 + sts_col)) = pa[i];\
    } while (0)

    #define CPA_B(kc, buf) do {                                                         \
        _Pragma("unroll")                                                               \
        for (int j = 0; j < 4; j++) {                                                   \
            int c = tid + 256 * j;                                                      \
            int row = c >> 2, cg = c & 3;                                               \
            cpa16(bsb + (buf) * bbufoff + SW64(row * 64 + cg * 16),                     \
                  Bb + (size_t)row * K + (kc) + cg * 8);                                \
        }                                                                               \
    } while (0)

    const int KT = K >> 5;
    CPA_B(0, 0);
    CPA_COMMIT();
    LD_A(0);
    ST_A(0);
    CPA_WAIT0();
    __syncthreads();

    for (int kt = 0; kt < KT; kt++) {
        const int buf = kt & 1;
        if (kt + 1 < KT) {
            CPA_B((kt + 1) * 32, buf ^ 1);
            CPA_COMMIT();
            LD_A((kt + 1) * 32);
        }

        const uint32_t ab = asb + buf * abufoff;
        const uint32_t bb = bsb + buf * bbufoff;
        #pragma unroll
        for (int ks = 0; ks < 2; ks++) {
            uint32_t af[2][4], bfq[4][4];
            #pragma unroll
            for (int mt = 0; mt < 2; mt++)
                ldmx4(af[mt], ab + SW64((wr * 32 + mt * 16 + a_row) * 64 + a_col + ks * 32));
            #pragma unroll
            for (int p = 0; p < 4; p++)
                ldmx4(bfq[p], bb + SW64((wc * 64 + p * 16 + b_row) * 64 + b_col + ks * 32));
            #pragma unroll
            for (int mt = 0; mt < 2; mt++)
                #pragma unroll
                for (int nt = 0; nt < 8; nt++)
                    mma_bf16(acc[mt][nt], af[mt], &bfq[nt >> 1][(nt & 1) * 2]);
        }

        if (kt + 1 < KT) {
            ST_A(buf ^ 1);
            CPA_WAIT0();
            __syncthreads();
        }
    }
    #undef LD_A
    #undef ST_A
    #undef CPA_B

    float sp[2][2] = {{0.f,0.f},{0.f,0.f}};
    float qp[2][2] = {{0.f,0.f},{0.f,0.f}};
    #pragma unroll
    for (int mt = 0; mt < 2; mt++) {
        const int r0 = brow + wr * 32 + mt * 16 + gid;
        const int r1 = r0 + 8;
        #pragma unroll
        for (int nt = 0; nt < 8; nt++) {
            const int col = wc * 64 + nt * 8 + 2 * tig;
            const float b0 = bias[col], b1 = bias[col + 1];
            float2 e0 = *reinterpret_cast<const float2*>(resid + (size_t)r0 * 256 + col);
            float2 e1 = *reinterpret_cast<const float2*>(resid + (size_t)r1 * 256 + col);
            acc[mt][nt][0] += b0 + e0.x;  acc[mt][nt][1] += b1 + e0.y;
            acc[mt][nt][2] += b0 + e1.x;  acc[mt][nt][3] += b1 + e1.y;
            sp[mt][0] += acc[mt][nt][0] + acc[mt][nt][1];
            sp[mt][1] += acc[mt][nt][2] + acc[mt][nt][3];
            qp[mt][0] += acc[mt][nt][0]*acc[mt][nt][0] + acc[mt][nt][1]*acc[mt][nt][1];
            qp[mt][1] += acc[mt][nt][2]*acc[mt][nt][2] + acc[mt][nt][3]*acc[mt][nt][3];
        }
    }
    #pragma unroll
    for (int o = 1; o <= 2; o <<= 1) {
        #pragma unroll
        for (int mt = 0; mt < 2; mt++)
            #pragma unroll
            for (int rr = 0; rr < 2; rr++) {
                sp[mt][rr] += __shfl_xor_sync(0xffffffffu, sp[mt][rr], o);
                qp[mt][rr] += __shfl_xor_sync(0xffffffffu, qp[mt][rr], o);
            }
    }
    if (tig == 0) {
        #pragma unroll
        for (int mt = 0; mt < 2; mt++)
            #pragma unroll
            for (int rr = 0; rr < 2; rr++) {
                const int rl = wr * 32 + mt * 16 + rr * 8 + gid;
                s_sum[rl][wc] = sp[mt][rr];
                s_sq [rl][wc] = qp[mt][rr];
            }
    }
    __syncthreads();
    if (tid < 64) {
        float S  = s_sum[tid][0] + s_sum[tid][1] + s_sum[tid][2] + s_sum[tid][3];
        float S2 = s_sq [tid][0] + s_sq [tid][1] + s_sq [tid][2] + s_sq [tid][3];
        const float mean = S * (1.f / 256.f);
        s_mean[tid] = mean;
        s_rstd[tid] = rsqrtf(S2 * (1.f / 256.f) - mean * mean + 1e-5f);
    }
    __syncthreads();

    #pragma unroll
    for (int mt = 0; mt < 2; mt++) {
        const int rl0 = wr * 32 + mt * 16 + gid;
        const int rl1 = rl0 + 8;
        const float m0 = s_mean[rl0], rs0 = s_rstd[rl0];
        const float m1 = s_mean[rl1], rs1 = s_rstd[rl1];
        const int r0 = brow + rl0, r1 = brow + rl1;
        #pragma unroll
        for (int nt = 0; nt < 8; nt++) {
            const int col = wc * 64 + nt * 8 + 2 * tig;
            float2 gg = *reinterpret_cast<const float2*>(g  + col);
            float2 ee = *reinterpret_cast<const float2*>(be + col);
            float2 u, v;
            u.x = (acc[mt][nt][0] - m0) * rs0 * gg.x + ee.x;
            u.y = (acc[mt][nt][1] - m0) * rs0 * gg.y + ee.y;
            v.x = (acc[mt][nt][2] - m1) * rs1 * gg.x + ee.x;
            v.y = (acc[mt][nt][3] - m1) * rs1 * gg.y + ee.y;
            *reinterpret_cast<float2*>(Out + (size_t)r0 * 256 + col) = u;
            *reinterpret_cast<float2*>(Out + (size_t)r1 * 256 + col) = v;
        }
    }
}

// ================= bf16x3 GEMM (oa): ~fp32 precision =================
__global__ void __launch_bounds__(256, 2) mma_gemm_x3(
    const float* __restrict__ A, const float* __restrict__ A2,
    const __nv_bfloat16* __restrict__ Bh, const __nv_bfloat16* __restrict__ Bl,
    const float* __restrict__ bias, float* __restrict__ C,
    int M, int N, int K)
{
    __shared__ __align__(128) __nv_bfloat16 Ahs[128 * 32];
    __shared__ __align__(128) __nv_bfloat16 Als[128 * 32];
    __shared__ __align__(128) __nv_bfloat16 Bhs[128 * 32];
    __shared__ __align__(128) __nv_bfloat16 Bls[128 * 32];

    const int tid  = threadIdx.x;
    const int lane = tid & 31;
    const int wid  = tid >> 5;
    const int wr   = wid & 1;
    const int wc   = wid >> 1;
    const int gid  = lane >> 2;
    const int tig  = lane & 3;
    const int brow = blockIdx.y * 128;
    const int bcol = blockIdx.x * 128;

    const int r_st = tid >> 3;
    const int kq   = (tid & 7) * 4;
    const int sts_col = (tid & 7) * 8;
    const int b_row_cp = tid >> 2;
    const int b_cg     = (tid & 3);

    float acc[4][4][4];
    #pragma unroll
    for (int i = 0; i < 4; i++)
        #pragma unroll
        for (int j = 0; j < 4; j++)
            #pragma unroll
            for (int l = 0; l < 4; l++) acc[i][j][l] = 0.f;

    const uint32_t ahb = (uint32_t)__cvta_generic_to_shared(&Ahs[0]);
    const uint32_t alb = (uint32_t)__cvta_generic_to_shared(&Als[0]);
    const uint32_t bhb = (uint32_t)__cvta_generic_to_shared(&Bhs[0]);
    const uint32_t blb = (uint32_t)__cvta_generic_to_shared(&Bls[0]);

    const int a_row = (lane & 7) + ((lane >> 3) & 1) * 8;
    const int a_col = (lane >> 4) * 16;
    const int b_row = (lane & 7) + ((lane >> 4) & 1) * 8;
    const int b_col = ((lane >> 3) & 1) * 16;

    uint2 pah[4], pal[4];

    #define LD_AX(kc) do {                                                              \
        _Pragma("unroll")                                                               \
        for (int i = 0; i < 4; i++) {                                                   \
            int gr = brow + r_st + 32 * i; if (gr >= M) gr = M - 1;                     \
            float4 v  = *reinterpret_cast<const float4*>(A  + (size_t)gr * K + (kc) + kq);\
            float4 v2 = *reinterpret_cast<const float4*>(A2 + (size_t)gr * K + (kc) + kq);\
            v.x += v2.x; v.y += v2.y; v.z += v2.z; v.w += v2.w;                         \
            __nv_bfloat162 h0 = __floats2bfloat162_rn(v.x, v.y);                        \
            __nv_bfloat162 h1 = __floats2bfloat162_rn(v.z, v.w);                        \
            float2 f0 = __bfloat1622float2(h0);                                         \
            float2 f1 = __bfloat1622float2(h1);                                         \
            pah[i].x = *reinterpret_cast<uint32_t*>(&h0);                               \
            pah[i].y = *reinterpret_cast<uint32_t*>(&h1);                               \
            pal[i].x = packbf(v.x - f0.x, v.y - f0.y);                                  \
            pal[i].y = packbf(v.z - f1.x, v.w - f1.y);                                  \
        }                                                                               \
    } while (0)

    #define ST_AX() do {                                                                \
        char* sh = reinterpret_cast<char*>(&Ahs[0]);                                    \
        char* sl = reinterpret_cast<char*>(&Als[0]);                                    \
        _Pragma("unroll")                                                               \
        for (int i = 0; i < 4; i++) {                                                   \
            uint32_t o = SW64((r_st + 32 * i) * 64 + sts_col);                          \
            *reinterpret_cast<uint2*>(sh + o) = pah[i];                                 \
            *reinterpret_cast<uint2*>(sl + o) = pal[i];                                 \
        }                                                                               \
    } while (0)

    #define CPA_BX(kc) do {                                                             \
        _Pragma("unroll")                                                               \
        for (int j = 0; j < 2; j++) {                                                   \
            int row = b_row_cp + 64 * j;                                                \
            uint32_t o = SW64(row * 64 + b_cg * 16);                                    \
            size_t gsrc = (size_t)(bcol + row) * K + (kc) + b_cg * 8;                   \
            cpa16(bhb + o, Bh + gsrc);                                                  \
            cpa16(blb + o, Bl + gsrc);                                                  \
        }                                                                               \
    } while (0)

    const int KT = K >> 5;
    LD_AX(0);
    for (int kt = 0; kt < KT; kt++) {
        if (kt) __syncthreads();
        ST_AX();
        CPA_BX(kt * 32);
        CPA_COMMIT();
        if (kt + 1 < KT) LD_AX((kt + 1) * 32);
        CPA_WAIT0();
        __syncthreads();

        #pragma unroll
        for (int ks = 0; ks < 2; ks++) {
            uint32_t afh[4][4], bfh[2][4];
            #pragma unroll
            for (int mt = 0; mt < 4; mt++)
                ldmx4(afh[mt], ahb + SW64((wr * 64 + mt * 16 + a_row) * 64 + a_col + ks * 32));
            #pragma unroll
            for (int p = 0; p < 2; p++)
                ldmx4(bfh[p], bhb + SW64((wc * 32 + p * 16 + b_row) * 64 + b_col + ks * 32));
            #pragma unroll
            for (int mt = 0; mt < 4; mt++)
                #pragma unroll
                for (int nt = 0; nt < 4; nt++)
                    mma_bf16(acc[mt][nt], afh[mt], &bfh[nt >> 1][(nt & 1) * 2]);

            {
                uint32_t bfl[2][4];
                #pragma unroll
                for (int p = 0; p < 2; p++)
                    ldmx4(bfl[p], blb + SW64((wc * 32 + p * 16 + b_row) * 64 + b_col + ks * 32));
                #pragma unroll
                for (int mt = 0; mt < 4; mt++)
                    #pragma unroll
                    for (int nt = 0; nt < 4; nt++)
                        mma_bf16(acc[mt][nt], afh[mt], &bfl[nt >> 1][(nt & 1) * 2]);
            }
            {
                uint32_t afl[4][4];
                #pragma unroll
                for (int mt = 0; mt < 4; mt++)
                    ldmx4(afl[mt], alb + SW64((wr * 64 + mt * 16 + a_row) * 64 + a_col + ks * 32));
                #pragma unroll
                for (int mt = 0; mt < 4; mt++)
                    #pragma unroll
                    for (int nt = 0; nt < 4; nt++)
                        mma_bf16(acc[mt][nt], afl[mt], &bfh[nt >> 1][(nt & 1) * 2]);
            }
        }
    }
    #undef LD_AX
    #undef ST_AX
    #undef CPA_BX

    #pragma unroll
    for (int mt = 0; mt < 4; mt++) {
        const int r0 = brow + wr * 64 + mt * 16 + gid;
        const int r1 = r0 + 8;
        const bool v0 = r0 < M, v1 = r1 < M;
        #pragma unroll
        for (int nt = 0; nt < 4; nt++) {
            const int col = bcol + wc * 32 + nt * 8 + 2 * tig;
            const float b0 = bias[col], b1 = bias[col + 1];
            float2 u, v;
            u.x = acc[mt][nt][0] + b0; u.y = acc[mt][nt][1] + b1;
            v.x = acc[mt][nt][2] + b0; v.y = acc[mt][nt][3] + b1;
            if (v0) *reinterpret_cast<float2*>(C + (size_t)r0 * N + col) = u;
            if (v1) *reinterpret_cast<float2*>(C + (size_t)r1 * N + col) = v;
        }
    }
}

// ---------------- weight prep V: Wv transpose -> bf16 (main stream) -------------
__global__ void wprepV_kernel(const float* __restrict__ Wv, __nv_bfloat16* __restrict__ WvT)
{
    __shared__ float t[32][33];
    const int bx = blockIdx.x * 32;
    const int by = blockIdx.y * 32;
    const int x = threadIdx.x, y = threadIdx.y;
    #pragma unroll
    for (int i = 0; i < 32; i += 8)
        t[y + i][x] = Wv[(size_t)(by + y + i) * DIM + bx + x];
    __syncthreads();
    #pragma unroll
    for (int i = 0; i < 32; i += 8)
        WvT[(size_t)(bx + y + i) * DIM + by + x] = __float2bfloat16(t[x][y + i]);
}

// ---------------- weight prep R: Wout/W1/W2 transpose + oa concat (stream 2) -----
__global__ void wprepR_kernel(const float* __restrict__ Wo,  __nv_bfloat16* __restrict__ WoT,
                              const float* __restrict__ W1,  __nv_bfloat16* __restrict__ W1T,
                              const float* __restrict__ W2,  __nv_bfloat16* __restrict__ W2T,
                              const float* __restrict__ Woff, const float* __restrict__ boff,
                              const float* __restrict__ Watt, const float* __restrict__ batt,
                              __nv_bfloat16* __restrict__ WoaTh, __nv_bfloat16* __restrict__ WoaTl,
                              float* __restrict__ boa)
{
    __shared__ float t[32][33];
    const int x = threadIdx.x, y = threadIdx.y;
    const int z = blockIdx.z;

    if (z == 3) {
        const int bx = blockIdx.x * 32;
        const int by = blockIdx.y * 32;
        if (bx >= NOA || by >= DIM) return;
        const bool isAtt = (bx >= 256);
        const float* W = isAtt ? Watt : Woff;
        const int    nN = isAtt ? 128 : 256;
        const int    nb = isAtt ? bx - 256 : bx;
        #pragma unroll
        for (int i = 0; i < 32; i += 8)
            t[y + i][x] = W[(size_t)(by + y + i) * nN + nb + x];
        __syncthreads();
        #pragma unroll
        for (int i = 0; i < 32; i += 8) {
            float w = t[x][y + i];
            __nv_bfloat16 h = __float2bfloat16(w);
            size_t idx = (size_t)(bx + y + i) * DIM + by + x;
            WoaTh[idx] = h;
            WoaTl[idx] = __float2bfloat16(w - __bfloat162float(h));
        }
        if (blockIdx.y == 0 && y == 0) {
            int n = bx + x;
            boa[n] = (n < 256) ? boff[n] : batt[n - 256];
        }
        return;
    }

    const float* W; __nv_bfloat16* Wt; int K, N;
    switch (z) {
        case 0: W = Wo; Wt = WoT; K = DIM; N = DIM; break;
        case 1: W = W1; Wt = W1T; K = DIM; N = DFF; break;
        default:W = W2; Wt = W2T; K = DFF; N = DIM; break;
    }
    const int bx = blockIdx.x * 32;
    const int by = blockIdx.y * 32;
    if (bx >= N || by >= K) return;
    #pragma unroll
    for (int i = 0; i < 32; i += 8)
        t[y + i][x] = W[(size_t)(by + y + i) * N + bx + x];
    __syncthreads();
    #pragma unroll
    for (int i = 0; i < 32; i += 8)
        Wt[(size_t)(bx + y + i) * K + by + x] = __float2bfloat16(t[x][y + i]);
}

// ---------------- MS-deform sampling v5 (plateaued — frozen) ----------
__device__ __forceinline__ void msda_corners(
    int l, float2 off, float refx, float refy, float wi,
    uint32_t* q, float* u)
{
    const int Hl = c_H[l], Wl = c_W[l], st = c_S[l];
    const float x = refx * (float)Wl + off.x - 0.5f;
    const float y = refy * (float)Hl + off.y - 0.5f;
    const float x0f = floorf(x), y0f = floorf(y);
    const float fx = x - x0f, fy = y - y0f;
    const int x0 = (int)x0f, y0 = (int)y0f;
    const int x1 = x0 + 1,   y1 = y0 + 1;
    const float vx0 = (x0 >= 0 && x0 < Wl) ? 1.f : 0.f;
    const float vx1 = (x1 >= 0 && x1 < Wl) ? 1.f : 0.f;
    const float vy0 = (y0 >= 0 && y0 < Hl) ? 1.f : 0.f;
    const float vy1 = (y1 >= 0 && y1 < Hl) ? 1.f : 0.f;
    const int xc0 = min(max(x0, 0), Wl - 1), xc1 = min(max(x1, 0), Wl - 1);
    const int yc0 = min(max(y0, 0), Hl - 1), yc1 = min(max(y1, 0), Hl - 1);
    q[0] = (uint32_t)(st + yc0 * Wl + xc0) * 512u;
    q[1] = (uint32_t)(st + yc0 * Wl + xc1) * 512u;
    q[2] = (uint32_t)(st + yc1 * Wl + xc0) * 512u;
    q[3] = (uint32_t)(st + yc1 * Wl + xc1) * 512u;
    u[0] = (1.f - fx) * (1.f - fy) * vx0 * vy0 * wi;
    u[1] = fx * (1.f - fy) * vx1 * vy0 * wi;
    u[2] = (1.f - fx) * fy * vx0 * vy1 * wi;
    u[3] = fx * fy * vx1 * vy1 * wi;
}

__global__ void __launch_bounds__(256) msda_kernel(
    const __nv_bfloat16* __restrict__ value,
    const float* __restrict__ oa,
    const float* __restrict__ refpts,
    float* __restrict__ samp)
{
    const int nq   = blockIdx.x * 4 + (threadIdx.x >> 6);
    const int t64  = threadIdx.x & 63;
    const int w    = t64 >> 5;
    const int lane = threadIdx.x & 31;
    const int g    = lane >> 3;
    const int ci   = lane & 7;
    const int h    = w * 4 + g;
    const int n    = nq / LQ;

    const float lg0 = oa[(size_t)nq * NOA + 256 + h * 16 + ci];
    const float lg1 = oa[(size_t)nq * NOA + 256 + h * 16 + ci + 8];
    float m = fmaxf(lg0, lg1);
    #pragma unroll
    for (int o = 4; o > 0; o >>= 1) m = fmaxf(m, __shfl_xor_sync(0xffffffffu, m, o, 8));
    const float e0 = __expf(lg0 - m), e1 = __expf(lg1 - m);
    float s = e0 + e1;
    #pragma unroll
    for (int o = 4; o > 0; o >>= 1) s += __shfl_xor_sync(0xffffffffu, s, o, 8);
    const float wi0 = e0 / s, wi1 = e1 / s;

    const float2 off0 = *reinterpret_cast<const float2*>(oa + (size_t)nq * NOA + h * 32 + 2 * ci);
    const float2 off1 = *reinterpret_cast<const float2*>(oa + (size_t)nq * NOA + h * 32 + 2 * (ci + 8));
    float2 refv = make_float2(0.f, 0.f);
    if (lane < 4) refv = *reinterpret_cast<const float2*>(refpts + (size_t)nq * 8 + 2 * lane);
    const int l0 = ci >> 2;
    const int l1 = l0 + 2;
    const float rx0 = __shfl_sync(0xffffffffu, refv.x, l0);
    const float ry0 = __shfl_sync(0xffffffffu, refv.y, l0);
    const float rx1 = __shfl_sync(0xffffffffu, refv.x, l1);
    const float ry1 = __shfl_sync(0xffffffffu, refv.y, l1);

    uint32_t q0[4], q1[4];
    float    u0[4], u1[4];
    msda_corners(l0, off0, rx0, ry0, wi0, q0, u0);
    msda_corners(l1, off1, rx1, ry1, wi1, q1, u1);

    const char* vb = reinterpret_cast<const char*>(
        value + ((size_t)n * LIN * HEADS + h) * HD + 4 * ci);

    float4 acc = make_float4(0.f, 0.f, 0.f, 0.f);

    #define GATHER(QARR, UARR, I) do {                                                  \
        const int src = g * 8 + (I);                                                    \
        const uint32_t qa = __shfl_sync(0xffffffffu, (QARR)[0], src);                   \
        const uint32_t qb = __shfl_sync(0xffffffffu, (QARR)[1], src);                   \
        const uint32_t qc = __shfl_sync(0xffffffffu, (QARR)[2], src);                   \
        const uint32_t qd = __shfl_sync(0xffffffffu, (QARR)[3], src);                   \
        const float ua = __shfl_sync(0xffffffffu, (UARR)[0], src);                      \
        const float ub = __shfl_sync(0xffffffffu, (UARR)[1], src);                      \
        const float uc = __shfl_sync(0xffffffffu, (UARR)[2], src);                      \
        const float ud = __shfl_sync(0xffffffffu, (UARR)[3], src);                      \
        const uint2 va = *reinterpret_cast<const uint2*>(vb + qa);                      \
        const uint2 vvb = *reinterpret_cast<const uint2*>(vb + qb);                     \
        const uint2 vc = *reinterpret_cast<const uint2*>(vb + qc);                      \
        const uint2 vd = *reinterpret_cast<const uint2*>(vb + qd);                      \
        float2 alo = __bfloat1622float2(*reinterpret_cast<const __nv_bfloat162*>(&va.x)); \
        float2 ahi = __bfloat1622float2(*reinterpret_cast<const __nv_bfloat162*>(&va.y)); \
        float2 blo = __bfloat1622float2(*reinterpret_cast<const __nv_bfloat162*>(&vvb.x)); \
        float2 bhi = __bfloat1622float2(*reinterpret_cast<const __nv_bfloat162*>(&vvb.y)); \
        float2 clo = __bfloat1622float2(*reinterpret_cast<const __nv_bfloat162*>(&vc.x)); \
        float2 chi = __bfloat1622float2(*reinterpret_cast<const __nv_bfloat162*>(&vc.y)); \
        float2 dlo = __bfloat1622float2(*reinterpret_cast<const __nv_bfloat162*>(&vd.x)); \
        float2 dhi = __bfloat1622float2(*reinterpret_cast<const __nv_bfloat162*>(&vd.y)); \
        acc.x += ua * alo.x + ub * blo.x + uc * clo.x + ud * dlo.x;                     \
        acc.y += ua * alo.y + ub * blo.y + uc * clo.y + ud * dlo.y;                     \
        acc.z += ua * ahi.x + ub * bhi.x + uc * chi.x + ud * dhi.x;                     \
        acc.w += ua * ahi.y + ub * bhi.y + uc * chi.y + ud * dhi.y;                     \
    } while (0)

    #pragma unroll
    for (int i = 0; i < 8; i++) GATHER(q0, u0, i);
    #pragma unroll
    for (int i = 0; i < 8; i++) GATHER(q1, u1, i);
    #undef GATHER

    *reinterpret_cast<float4*>(samp + (size_t)nq * 256 + h * 32 + 4 * ci) = acc;
}

// ---------------- launch ----------------
extern "C" void kernel_launch(void* const* d_in, const int* in_sizes, int n_in,
                              void* d_out, int out_size)
{
    const float* pre_tgt  = (const float*)d_in[0];
    const float* pre_qpos = (const float*)d_in[1];
    const float* src      = (const float*)d_in[2];
    const float* ref_pts  = (const float*)d_in[3];
    const unsigned char* mask = (const unsigned char*)d_in[4];
    const float* W_value = (const float*)d_in[7];
    const float* b_value = (const float*)d_in[8];
    const float* W_off   = (const float*)d_in[9];
    const float* b_off   = (const float*)d_in[10];
    const float* W_attn  = (const float*)d_in[11];
    const float* b_attn  = (const float*)d_in[12];
    const float* W_out   = (const float*)d_in[13];
    const float* b_out   = (const float*)d_in[14];
    const float* g1      = (const float*)d_in[15];
    const float* be1     = (const float*)d_in[16];
    const float* W1      = (const float*)d_in[17];
    const float* b1      = (const float*)d_in[18];
    const float* W2      = (const float*)d_in[19];
    const float* b2      = (const float*)d_in[20];
    const float* g3      = (const float*)d_in[21];
    const float* be3     = (const float*)d_in[22];

    __nv_bfloat16 *p_value, *p_WvTb, *p_WoutTb, *p_W1Tb, *p_W2Tb, *p_WoaTh, *p_WoaTl;
    float *p_oa, *p_samp, *p_tgt, *p_ffh, *p_boa;
    cudaGetSymbolAddress((void**)&p_value, g_value);
    cudaGetSymbolAddress((void**)&p_oa,    g_oa);
    cudaGetSymbolAddress((void**)&p_samp,  g_samp);
    cudaGetSymbolAddress((void**)&p_tgt,   g_tgt);
    cudaGetSymbolAddress((void**)&p_ffh,   g_ffh);
    cudaGetSymbolAddress((void**)&p_WvTb,  g_WvTb);
    cudaGetSymbolAddress((void**)&p_WoutTb,g_WoutTb);
    cudaGetSymbolAddress((void**)&p_W1Tb,  g_W1Tb);
    cudaGetSymbolAddress((void**)&p_W2Tb,  g_W2Tb);
    cudaGetSymbolAddress((void**)&p_WoaTh, g_WoaTh);
    cudaGetSymbolAddress((void**)&p_WoaTl, g_WoaTl);
    cudaGetSymbolAddress((void**)&p_boa,   g_boa);

    // side stream + events for fork-join (created once; graph-capture-compatible
    // event fork pattern, identical launch set on every call)
    static cudaStream_t s2 = nullptr;
    static cudaEvent_t evFork = nullptr, evJoin = nullptr;
    if (s2 == nullptr) {
        cudaStreamCreateWithFlags(&s2, cudaStreamNonBlocking);
        cudaEventCreateWithFlags(&evFork, cudaEventDisableTiming);
        cudaEventCreateWithFlags(&evJoin, cudaEventDisableTiming);
    }

    const int MV = NB * LIN;   // 174080
    dim3 tb(32, 8);

    // ---- fork: branch B (s2) = wprepR + oa GEMM; branch A (main) = wprepV + value GEMM
    cudaEventRecord(evFork, 0);
    cudaStreamWaitEvent(s2, evFork, 0);

    // branch B (stream s2)
    wprepR_kernel<<<dim3(16, 16, 4), tb, 0, s2>>>(
        W_out, p_WoutTb, W1, p_W1Tb, W2, p_W2Tb,
        W_off, b_off, W_attn, b_attn, p_WoaTh, p_WoaTl, p_boa);
    mma_gemm_x3<<<dim3(NOA / 128, (NQ + 127) / 128), 256, 0, s2>>>(
        pre_tgt, pre_qpos, p_WoaTh, p_WoaTl, p_boa, p_oa, NQ, NOA, DIM);
    cudaEventRecord(evJoin, s2);

    // branch A (main stream)
    wprepV_kernel<<<dim3(8, 8), tb>>>(W_value, p_WvTb);
    mma_gemm_v6<0, true, 1><<<dim3(2, MV / 128), 256>>>(
        src, p_WvTb, b_value, p_value, MV, DIM, DIM, mask);

    // ---- join
    cudaStreamWaitEvent(0, evJoin, 0);

    // sampling (needs value + oa)
    msda_kernel<<<NQ / 4, 256>>>(p_value, p_oa, ref_pts, p_samp);
    // tgt = LN(pre_tgt + samp @ Wout + bout)
    mma_gemm_ln<<<NQ / 64, 256>>>(
        p_samp, p_WoutTb, b_out, pre_tgt, g1, be1, p_tgt, NQ, DIM);
    // ffh = relu(tgt @ W1 + b1)
    mma_gemm_v6<1, false, 0><<<dim3(4, (NQ + 127) / 128), 256>>>(
        p_tgt, p_W1Tb, b1, p_ffh, NQ, DFF, DIM, nullptr);
    // out = LN(tgt + ffh @ W2 + b2)
    mma_gemm_ln<<<NQ / 64, 256>>>(
        p_ffh, p_W2Tb, b2, p_tgt, g3, be3, (float*)d_out, NQ, DFF);
}